// round 11
// baseline (speedup 1.0000x reference)
#include <cuda_runtime.h>
#include <cuda_fp16.h>
#include <math.h>
#include <stdint.h>

#define BB 4
#define LL 2048
#define DD 512
#define HH 8
#define DK 64
#define FFD 2048
#define NTOP 40
#define SK 40
#define BH (BB*HH)
#define ROWS (BB*LL)
#define QS 1536

__device__ uint16_t g_QKVh[ROWS*QS];      // fp16 Q|K|V
__device__ float g_h1[ROWS*DD];
__device__ float g_t0[ROWS*DD];
__device__ float g_M[BH*LL];
__device__ float g_vmean[BH*DK];
__device__ int   g_top[BH*NTOP];
__device__ float g_bcat[QS];
__device__ float g_sc[BH*NTOP*LL];
__device__ float g_mx[BH*NTOP];
__device__ float g_inv[BH*NTOP];
__device__ float g_part[4*BH*NTOP*DK];
__device__ uint16_t g_Cf16[ROWS*DD];      // x-f16 for QKV GEMM, later ctx for Wo
__device__ uint16_t g_H1f16[ROWS*DD];
__device__ uint16_t g_Gf16[ROWS*FFD];
__device__ uint16_t g_Wf16h[12*DD*DD];
__device__ uint16_t g_Wf16l[12*DD*DD];

__device__ __forceinline__ uint32_t smem_u32(const void* p){
    uint32_t a; asm("{ .reg .u64 t; cvta.to.shared.u64 t, %1; cvt.u32.u64 %0, t; }":"=r"(a):"l"(p)); return a;
}
__device__ __forceinline__ void cpasync16(uint32_t dst, const void* src){
    asm volatile("cp.async.cg.shared.global [%0], [%1], 16;" :: "r"(dst), "l"(src));
}
__device__ __forceinline__ void ldsm4(uint32_t* r, uint32_t addr){
    asm volatile("ldmatrix.sync.aligned.m8n8.x4.shared.b16 {%0,%1,%2,%3}, [%4];"
        : "=r"(r[0]),"=r"(r[1]),"=r"(r[2]),"=r"(r[3]) : "r"(addr));
}
__device__ __forceinline__ void mma_fp(float* c, const uint32_t* a, const uint32_t* b){
    asm volatile("mma.sync.aligned.m16n8k16.row.col.f32.f16.f16.f32 "
        "{%0,%1,%2,%3}, {%4,%5,%6,%7}, {%8,%9}, {%0,%1,%2,%3};"
        : "+f"(c[0]),"+f"(c[1]),"+f"(c[2]),"+f"(c[3])
        : "r"(a[0]),"r"(a[1]),"r"(a[2]),"r"(a[3]),"r"(b[0]),"r"(b[1]));
}
__device__ __forceinline__ uint32_t packh(__half a, __half b){
    return (uint32_t)__half_as_ushort(a) | ((uint32_t)__half_as_ushort(b)<<16);
}
__device__ __forceinline__ float2 h2f(uint32_t u){
    __half2 h = *reinterpret_cast<__half2*>(&u);
    return __half22float2(h);
}
// branchless exact-GELU (A&S 7.1.26 erf approx, max abs err 1.5e-7)
__device__ __forceinline__ float gelu_fast(float v){
    float av = fabsf(v);
    float t = __fdividef(1.0f, fmaf(0.70710678118654752440f*0.3275911f, av, 1.0f));
    float poly = t*(0.254829592f + t*(-0.284496736f + t*(1.421413741f + t*(-1.453152027f + t*1.061405429f))));
    float e = __expf(-0.5f*v*v);
    float erfv = copysignf(1.0f - poly*e, v);
    return 0.5f*v*(1.0f + erfv);
}

// =====================================================================
// HMMA GEMM: fp16 2-term (single-A x B-hi/lo), fp32 acc.
// BM=BN=128, BK=32, 256 thr, 2 CTAs/SM, 3-stage cp.async pipeline.
// OUTMODE: 0 = fp32 C; 2 = fp16 C16. ACT=1: GELU.
// =====================================================================
template<int ACT, int OUTMODE>
__global__ void __launch_bounds__(256,2)
gemm_hmma(const uint16_t* __restrict__ A0,
          const uint16_t* __restrict__ B0, const uint16_t* __restrict__ B1,
          const float* __restrict__ bias, float* __restrict__ C,
          uint16_t* __restrict__ C16, int K, int ldc)
{
    extern __shared__ __align__(16) char sm[];
    const int t = threadIdx.x, lane = t&31, w = t>>5;
    const int wm = w>>2, wn = w&3;
    const int bm = blockIdx.y*128, bn = blockIdx.x*128;
    const int group = lane>>2, tig = lane&3;
    const uint32_t sbase = smem_u32(sm);
    const int STAGE = 30720;

    float acc[4][4][4];
    #pragma unroll
    for (int i=0;i<4;i++)
        #pragma unroll
        for (int j=0;j<4;j++)
            #pragma unroll
            for (int r=0;r<4;r++) acc[i][j][r]=0.f;

    const uint16_t* srcs[3] = {A0, B0, B1};
    const int nch = K>>5;
    #pragma unroll
    for (int pc=0; pc<2; pc++){
        const int k0 = pc<<5;
        const uint32_t dst0 = sbase + pc*STAGE;
        #pragma unroll
        for (int u=0; u<6; u++){
            int q = t + u*256;
            int tile = q>>9, rem = q&511;
            int r = rem>>2, c = rem&3;
            const uint16_t* src = srcs[tile] + (size_t)(((tile<1)?bm:bn) + r)*K + k0 + c*8;
            cpasync16(dst0 + tile*10240 + r*80 + c*16, src);
        }
        asm volatile("cp.async.commit_group;");
    }
    const int brow_off = ((lane>>4)<<3) + (lane&7);
    const int bk_half  = (lane>>3)&1;
    int buf = 0;
    for (int ch=0; ch<nch; ch++){
        if (ch+2 < nch){
            const int k0 = (ch+2)<<5;
            int nb = buf+2; if (nb>=3) nb-=3;
            const uint32_t dst0 = sbase + nb*STAGE;
            #pragma unroll
            for (int u=0; u<6; u++){
                int q = t + u*256;
                int tile = q>>9, rem = q&511;
                int r = rem>>2, c = rem&3;
                const uint16_t* src = srcs[tile] + (size_t)(((tile<1)?bm:bn) + r)*K + k0 + c*8;
                cpasync16(dst0 + tile*10240 + r*80 + c*16, src);
            }
            asm volatile("cp.async.commit_group;");
            asm volatile("cp.async.wait_group 2;");
        } else if (ch+1 < nch){
            asm volatile("cp.async.wait_group 1;");
        } else {
            asm volatile("cp.async.wait_group 0;");
        }
        __syncthreads();
        const uint32_t stg = sbase + buf*STAGE;
        #pragma unroll
        for (int kk=0; kk<2; kk++){
            uint32_t a_h[4][4];
            #pragma unroll
            for (int mt=0; mt<4; mt++){
                uint32_t ra = stg + (uint32_t)((wm*64 + mt*16 + (lane&15))*80 + (lane>>4)*16 + kk*32);
                ldsm4(a_h[mt], ra);
            }
            #pragma unroll
            for (int ntp=0; ntp<2; ntp++){
                uint32_t bh4[4], bl4[4];
                uint32_t rb = stg + 10240u +
                    (uint32_t)((wn*32 + ntp*16 + brow_off)*80 + bk_half*16 + kk*32);
                ldsm4(bh4, rb);
                ldsm4(bl4, rb + 10240u);
                #pragma unroll
                for (int mt=0; mt<4; mt++){
                    mma_fp(acc[mt][2*ntp+0], a_h[mt], &bh4[0]);
                    mma_fp(acc[mt][2*ntp+0], a_h[mt], &bl4[0]);
                    mma_fp(acc[mt][2*ntp+1], a_h[mt], &bh4[2]);
                    mma_fp(acc[mt][2*ntp+1], a_h[mt], &bl4[2]);
                }
            }
        }
        __syncthreads();
        buf++; if (buf>=3) buf=0;
    }
    #pragma unroll
    for (int mt=0; mt<4; mt++){
        #pragma unroll
        for (int nt=0; nt<4; nt++){
            int r0  = bm + wm*64 + mt*16 + group;
            int col = bn + wn*32 + nt*8 + tig*2;
            float bb0 = bias[col], bb1 = bias[col+1];
            #pragma unroll
            for (int hh2=0; hh2<2; hh2++){
                int row = r0 + hh2*8;
                float v0 = acc[mt][nt][hh2*2+0] + bb0;
                float v1 = acc[mt][nt][hh2*2+1] + bb1;
                if (ACT==1){ v0 = gelu_fast(v0); v1 = gelu_fast(v1); }
                if (OUTMODE==0){
                    *(float2*)(C + (size_t)row*ldc + col) = make_float2(v0, v1);
                } else {
                    *(uint32_t*)(C16 + (size_t)row*ldc + col) =
                        packh(__float2half(v0), __float2half(v1));
                }
            }
        }
    }
}

__global__ void convert_wf16(const float* __restrict__ src,
                             uint16_t* __restrict__ hi, uint16_t* __restrict__ lo, int n4)
{
    int i = blockIdx.x*256 + threadIdx.x;
    if (i>=n4) return;
    float4 v = ((const float4*)src)[i];
    __half h0=__float2half(v.x), h1=__float2half(v.y), h2=__float2half(v.z), h3=__float2half(v.w);
    __half l0=__float2half(v.x-__half2float(h0)), l1=__float2half(v.y-__half2float(h1));
    __half l2=__float2half(v.z-__half2float(h2)), l3=__float2half(v.w-__half2float(h3));
    ((uint2*)hi)[i] = make_uint2(packh(h0,h1), packh(h2,h3));
    ((uint2*)lo)[i] = make_uint2(packh(l0,l1), packh(l2,l3));
}

__global__ void convert_f16(const float* __restrict__ src, uint16_t* __restrict__ dst, int n4)
{
    int i = blockIdx.x*256 + threadIdx.x;
    if (i>=n4) return;
    float4 v = ((const float4*)src)[i];
    ((uint2*)dst)[i] = make_uint2(packh(__float2half(v.x), __float2half(v.y)),
                                  packh(__float2half(v.z), __float2half(v.w)));
}

__global__ void bias_concat(const float* __restrict__ bq, const float* __restrict__ bk,
                            const float* __restrict__ bv)
{
    int t = blockIdx.x*256 + threadIdx.x;
    if (t>=QS) return;
    g_bcat[t] = (t<512)? bq[t] : (t<1024)? bk[t-512] : bv[t-1024];
}

// one warp per (bh,i); fp16 Q/K, half2 loads, idx broadcast from regs
__global__ void sample_scores_kernel(const int* __restrict__ idxs)
{
    int g = blockIdx.x*8 + (threadIdx.x>>5);
    int lane = threadIdx.x&31;
    int i = g&(LL-1), bh = g>>11, b = bh>>3, h = bh&7;
    const uint32_t* qp = (const uint32_t*)(g_QKVh + (size_t)(b*LL+i)*QS + h*DK);
    float2 q = h2f(qp[lane]);
    int myi0 = idxs[i*SK + lane];
    int myi1 = (lane<8)? idxs[i*SK + 32 + lane] : 0;
    const uint16_t* kbase = g_QKVh + (size_t)b*LL*QS + 512 + h*DK;
    float mx = -INFINITY, sm = 0.f;
    #pragma unroll 4
    for (int j=0; j<SK; j++){
        int kidx = (j<32)? __shfl_sync(0xffffffffu, myi0, j)
                         : __shfl_sync(0xffffffffu, myi1, j-32);
        float2 kv = h2f(((const uint32_t*)(kbase + (size_t)kidx*QS))[lane]);
        float s = q.x*kv.x + q.y*kv.y;
        #pragma unroll
        for (int off=16; off; off>>=1) s += __shfl_xor_sync(0xffffffffu, s, off);
        mx = fmaxf(mx, s); sm += s;
    }
    if (lane==0) g_M[bh*LL+i] = mx - sm*(1.0f/LL);
}

__global__ void topk_kernel()
{
    int bh = blockIdx.x, t = threadIdx.x;
    __shared__ uint32_t su[LL];
    __shared__ int hist[256];
    __shared__ int s_bucket, s_taken;
    __shared__ int tsum[256];
    __shared__ int s_ctr;

    for (int l=t; l<LL; l+=256){
        uint32_t s = __float_as_uint(g_M[bh*LL+l]);
        su[l] = (s & 0x80000000u)? ~s : (s | 0x80000000u);
    }
    if (t==0) s_ctr = 0;
    __syncthreads();

    uint32_t prefix = 0;
    int remaining = NTOP;
    #pragma unroll
    for (int round=0; round<4; round++){
        int shift = 24 - round*8;
        hist[t] = 0;
        __syncthreads();
        for (int l=t; l<LL; l+=256){
            uint32_t u = su[l];
            bool m = (round==0) || (((u ^ prefix) >> (shift+8)) == 0u);
            if (m) atomicAdd(&hist[(u>>shift)&255], 1);
        }
        __syncthreads();
        if (t < 32){
            int loc[8], run = 0;
            #pragma unroll
            for (int k=0; k<8; k++){
                int b = 255 - (t*8 + k);
                loc[k] = run;
                run += hist[b];
            }
            int lane_total = run;
            int scan = lane_total;
            #pragma unroll
            for (int off=1; off<32; off<<=1){
                int v = __shfl_up_sync(0xffffffffu, scan, off);
                if (t >= off) scan += v;
            }
            int excl = scan - lane_total;
            #pragma unroll
            for (int k=0; k<8; k++){
                int b = 255 - (t*8 + k);
                int cumAbove = excl + loc[k];
                if (cumAbove < remaining && remaining <= cumAbove + hist[b]){
                    s_bucket = b;
                    s_taken  = cumAbove;
                }
            }
        }
        __syncthreads();
        prefix |= ((uint32_t)s_bucket) << shift;
        remaining -= s_taken;
        __syncthreads();
    }
    const uint32_t T = prefix;
    const int r = remaining;
    const int cnt_gt = NTOP - r;

    int base = t*8, c = 0;
    #pragma unroll
    for (int k=0; k<8; k++) if (su[base+k] == T) c++;
    tsum[t] = c;
    __syncthreads();
    for (int off=1; off<256; off<<=1){
        int v = (t>=off)? tsum[t-off] : 0;
        __syncthreads();
        tsum[t] += v;
        __syncthreads();
    }
    int excl = tsum[t] - c;
    #pragma unroll
    for (int k=0; k<8; k++){
        uint32_t u = su[base+k];
        if (u > T){
            int pos = atomicAdd(&s_ctr, 1);
            g_top[bh*NTOP + pos] = base + k;
        } else if (u == T){
            if (excl < r) g_top[bh*NTOP + cnt_gt + excl] = base + k;
            excl++;
        }
    }
}

__global__ void vmean_kernel()
{
    int bh = blockIdx.x, b = bh>>3, h = bh&7;
    int t = threadIdx.x, d2 = (t&31)*2, r0 = t>>5;   // 8 rows in flight, half2 per lane
    float s0 = 0.f, s1 = 0.f;
    for (int l=r0; l<LL; l+=8){
        float2 v = h2f(*(const uint32_t*)(g_QKVh + (size_t)(b*LL+l)*QS + 1024 + h*DK + d2));
        s0 += v.x; s1 += v.y;
    }
    __shared__ float red[2][256];
    red[0][t]=s0; red[1][t]=s1; __syncthreads();
    for (int k=128; k>=32; k>>=1){
        if (t<k){ red[0][t]+=red[0][t+k]; red[1][t]+=red[1][t+k]; }
        __syncthreads();
    }
    if (t<32){
        g_vmean[bh*DK + 2*t]   = red[0][t] * (1.0f/LL);
        g_vmean[bh*DK + 2*t+1] = red[1][t] * (1.0f/LL);
    }
}

__global__ void ctx_bcast_kernel(uint16_t* __restrict__ c16)
{
    int i = blockIdx.x*256 + threadIdx.x;
    int row = i>>8, c2 = (i&255)*2;
    int b = row>>11, h = c2>>6;
    const float* vm = g_vmean + (b*HH+h)*DK;
    *(uint32_t*)(c16 + (size_t)row*DD + c2) =
        packh(__float2half(vm[c2&63]), __float2half(vm[(c2&63)+1]));
}

__global__ void attn_scores_kernel()
{
    int kt = blockIdx.x, bh = blockIdx.y, b = bh>>3, h = bh&7;
    int t = threadIdx.x;
    __shared__ float sq[NTOP][64];
    __shared__ __align__(16) float Ks[128][68];
    __shared__ int tops[NTOP];
    if (t < NTOP) tops[t] = g_top[bh*NTOP + t];
    __syncthreads();
    const size_t qkv = (size_t)b*LL*QS;
    for (int idx=t; idx<NTOP*32; idx+=128){
        int qn = idx>>5, d2 = (idx&31)*2;
        float2 v = h2f(*(const uint32_t*)(g_QKVh + qkv + (size_t)tops[qn]*QS + h*DK + d2));
        sq[qn][d2] = v.x; sq[qn][d2+1] = v.y;
    }
    #pragma unroll
    for (int u=0; u<8; u++){
        int f = t + u*128;                 // [0,1024): 128 rows x 8 col-groups
        int r = f>>3, c = (f&7)*8;
        uint4 kv = *(const uint4*)(g_QKVh + qkv + (size_t)(kt*128+r)*QS + 512 + h*DK + c);
        float2 p0 = h2f(kv.x), p1 = h2f(kv.y), p2 = h2f(kv.z), p3 = h2f(kv.w);
        Ks[r][c+0]=p0.x; Ks[r][c+1]=p0.y; Ks[r][c+2]=p1.x; Ks[r][c+3]=p1.y;
        Ks[r][c+4]=p2.x; Ks[r][c+5]=p2.y; Ks[r][c+6]=p3.x; Ks[r][c+7]=p3.y;
    }
    __syncthreads();
    float acc[NTOP];
    #pragma unroll
    for (int qn=0; qn<NTOP; qn++) acc[qn]=0.f;
    for (int k2=0; k2<32; k2++){
        float2 kv = *(const float2*)(&Ks[t][k2*2]);
        #pragma unroll
        for (int qn=0; qn<NTOP; qn++){
            float2 qv = *(const float2*)(&sq[qn][k2*2]);
            acc[qn] += kv.x*qv.x + kv.y*qv.y;
        }
    }
    #pragma unroll
    for (int qn=0; qn<NTOP; qn++)
        g_sc[((size_t)bh*NTOP + qn)*LL + kt*128 + t] = acc[qn];
}

__global__ void attn_stats_kernel()
{
    int bh = blockIdx.x;
    int w = threadIdx.x>>5, lane = threadIdx.x&31;
    for (int j=0; j<5; j++){
        int qn = w*5 + j;
        const float* sp = g_sc + ((size_t)bh*NTOP + qn)*LL;
        float mx = -INFINITY;
        for (int i=lane; i<LL; i+=32) mx = fmaxf(mx, sp[i]);
        #pragma unroll
        for (int off=16; off; off>>=1) mx = fmaxf(mx, __shfl_xor_sync(0xffffffffu, mx, off));
        float sum = 0.f;
        for (int i=lane; i<LL; i+=32) sum += expf(sp[i]-mx);
        #pragma unroll
        for (int off=16; off; off>>=1) sum += __shfl_xor_sync(0xffffffffu, sum, off);
        if (lane==0){ g_mx[bh*NTOP+qn]=mx; g_inv[bh*NTOP+qn]=1.0f/sum; }
    }
}

__global__ void attn_pv_kernel()
{
    extern __shared__ __align__(16) float psm[];
    float* Vs  = psm;
    float* P   = psm + 8704;
    float* smx = psm + 8704 + 5160;
    int ks = blockIdx.x, bh = blockIdx.y, b = bh>>3, h = bh&7;
    int t = threadIdx.x;
    if (t < NTOP) smx[t] = g_mx[bh*NTOP + t];
    __syncthreads();
    const size_t qkv = (size_t)b*LL*QS;
    int qg = t>>5, d2 = (t&31)*2;
    float acc[5][2];
    #pragma unroll
    for (int j=0;j<5;j++){ acc[j][0]=0.f; acc[j][1]=0.f; }
    for (int kt=0; kt<4; kt++){
        int ktg = ks*4 + kt;
        #pragma unroll
        for (int u=0; u<4; u++){
            int f = t + u*256;             // [0,1024)
            int r = f>>3, c = (f&7)*8;
            uint4 vv = *(const uint4*)(g_QKVh + qkv + (size_t)(ktg*128+r)*QS + 1024 + h*DK + c);
            float2 p0 = h2f(vv.x), p1 = h2f(vv.y), p2 = h2f(vv.z), p3 = h2f(vv.w);
            float* dst = &Vs[r*68 + c];
            dst[0]=p0.x; dst[1]=p0.y; dst[2]=p1.x; dst[3]=p1.y;
            dst[4]=p2.x; dst[5]=p2.y; dst[6]=p3.x; dst[7]=p3.y;
        }
        #pragma unroll
        for (int u=0; u<20; u++){
            int idx = t + u*256;
            int qn = idx>>7, row = idx&127;
            float s = g_sc[((size_t)bh*NTOP + qn)*LL + ktg*128 + row];
            P[qn*129 + row] = expf(s - smx[qn]);
        }
        __syncthreads();
        for (int row=0; row<128; row++){
            float2 vv = *(const float2*)(&Vs[row*68 + d2]);
            #pragma unroll
            for (int j=0; j<5; j++){
                float p = P[(qg*5+j)*129 + row];
                acc[j][0] += p*vv.x;
                acc[j][1] += p*vv.y;
            }
        }
        __syncthreads();
    }
    #pragma unroll
    for (int j=0; j<5; j++){
        int qn = qg*5 + j;
        float* dst = g_part + ((size_t)(ks*BH + bh)*NTOP + qn)*DK + d2;
        dst[0] = acc[j][0];
        dst[1] = acc[j][1];
    }
}

__global__ void attn_combine_kernel(uint16_t* __restrict__ c16)
{
    int bh = blockIdx.x, b = bh>>3, h = bh&7;
    int t = threadIdx.x;
    __shared__ int tops[NTOP];
    __shared__ float sinv[NTOP];
    if (t < NTOP){ tops[t] = g_top[bh*NTOP+t]; sinv[t] = g_inv[bh*NTOP+t]; }
    __syncthreads();
    for (int e=t; e<NTOP*DK/2; e+=256){
        int qn = e>>5, d2 = (e&31)*2;
        float s0=0.f, s1=0.f;
        #pragma unroll
        for (int ks=0; ks<4; ks++){
            const float* pp = g_part + ((size_t)(ks*BH + bh)*NTOP + qn)*DK + d2;
            s0 += pp[0]; s1 += pp[1];
        }
        s0 *= sinv[qn]; s1 *= sinv[qn];
        size_t o = (size_t)(b*LL + tops[qn])*DD + h*DK + d2;
        *(uint32_t*)(c16 + o) = packh(__float2half(s0), __float2half(s1));
    }
}

template<int F16OUT>
__global__ void ln_add_kernel(const float* __restrict__ X, const float* __restrict__ Y,
                              const float* __restrict__ gg, const float* __restrict__ be,
                              float* __restrict__ out, uint16_t* __restrict__ o16)
{
    int row = blockIdx.x, t = threadIdx.x;
    float4 a = ((const float4*)(X + (size_t)row*DD))[t];
    float4 bq = ((const float4*)(Y + (size_t)row*DD))[t];
    float4 v = make_float4(a.x+bq.x, a.y+bq.y, a.z+bq.z, a.w+bq.w);
    float s = v.x+v.y+v.z+v.w;
    float ss = v.x*v.x+v.y*v.y+v.z*v.z+v.w*v.w;
    __shared__ float rs[128], rq[128];
    rs[t]=s; rq[t]=ss; __syncthreads();
    for (int k=64; k; k>>=1){ if (t<k){ rs[t]+=rs[t+k]; rq[t]+=rq[t+k]; } __syncthreads(); }
    float mean = rs[0]*(1.0f/DD);
    float var  = rq[0]*(1.0f/DD) - mean*mean;
    float rstd = rsqrtf(var + 1e-5f);
    float4 g4 = ((const float4*)gg)[t], b4 = ((const float4*)be)[t];
    float4 o;
    o.x=(v.x-mean)*rstd*g4.x+b4.x; o.y=(v.y-mean)*rstd*g4.y+b4.y;
    o.z=(v.z-mean)*rstd*g4.z+b4.z; o.w=(v.w-mean)*rstd*g4.w+b4.w;
    ((float4*)(out + (size_t)row*DD))[t] = o;
    if (F16OUT){
        ((uint2*)(o16 + (size_t)row*DD))[t] = make_uint2(
            packh(__float2half(o.x), __float2half(o.y)),
            packh(__float2half(o.z), __float2half(o.w)));
    }
}

extern "C" void kernel_launch(void* const* d_in, const int* in_sizes, int n_in,
                              void* d_out, int out_size)
{
    const float* x    = (const float*)d_in[0];
    const int*   idxs = (const int*)  d_in[1];
    const float* Wq = (const float*)d_in[2];  const float* bq = (const float*)d_in[3];
    const float* Wk = (const float*)d_in[4];  const float* bk = (const float*)d_in[5];
    const float* Wv = (const float*)d_in[6];  const float* bv = (const float*)d_in[7];
    const float* Wo = (const float*)d_in[8];  const float* bo = (const float*)d_in[9];
    const float* W1 = (const float*)d_in[10]; const float* b1 = (const float*)d_in[11];
    const float* W2 = (const float*)d_in[12]; const float* b2 = (const float*)d_in[13];
    const float* g1 = (const float*)d_in[14]; const float* be1 = (const float*)d_in[15];
    const float* g2 = (const float*)d_in[16]; const float* be2 = (const float*)d_in[17];
    float* out = (float*)d_out;

    float *H1,*T0,*BCAT;
    uint16_t *QKVH,*CF,*H1F,*GF,*WFH,*WFL;
    cudaGetSymbolAddress((void**)&QKVH, g_QKVh);
    cudaGetSymbolAddress((void**)&H1, g_h1);   cudaGetSymbolAddress((void**)&T0, g_t0);
    cudaGetSymbolAddress((void**)&BCAT, g_bcat);
    cudaGetSymbolAddress((void**)&CF, g_Cf16); cudaGetSymbolAddress((void**)&H1F, g_H1f16);
    cudaGetSymbolAddress((void**)&GF, g_Gf16);
    cudaGetSymbolAddress((void**)&WFH, g_Wf16h); cudaGetSymbolAddress((void**)&WFL, g_Wf16l);

    const int SMEM = 92160;
    cudaFuncSetAttribute(gemm_hmma<0,0>, cudaFuncAttributeMaxDynamicSharedMemorySize, SMEM);
    cudaFuncSetAttribute(gemm_hmma<0,2>, cudaFuncAttributeMaxDynamicSharedMemorySize, SMEM);
    cudaFuncSetAttribute(gemm_hmma<1,2>, cudaFuncAttributeMaxDynamicSharedMemorySize, SMEM);
    cudaFuncSetAttribute(attn_pv_kernel, cudaFuncAttributeMaxDynamicSharedMemorySize, 55616);

    const int DW = DD*DD;
    convert_wf16<<<DW/1024, 256>>>(Wq, WFH+0*DW, WFL+0*DW, DW/4);
    convert_wf16<<<DW/1024, 256>>>(Wk, WFH+1*DW, WFL+1*DW, DW/4);
    convert_wf16<<<DW/1024, 256>>>(Wv, WFH+2*DW, WFL+2*DW, DW/4);
    convert_wf16<<<DW/1024, 256>>>(Wo, WFH+3*DW, WFL+3*DW, DW/4);
    convert_wf16<<<DW*4/1024, 256>>>(W1, WFH+4*DW, WFL+4*DW, DW);
    convert_wf16<<<DW*4/1024, 256>>>(W2, WFH+8*DW, WFL+8*DW, DW);
    convert_f16<<<ROWS*DD/1024, 256>>>(x, CF, ROWS*DD/4);
    bias_concat<<<QS/256, 256>>>(bq, bk, bv);

    dim3 gQKV(QS/128, ROWS/128), gD(DD/128, ROWS/128), gF(FFD/128, ROWS/128);
    gemm_hmma<0,2><<<gQKV, 256, SMEM>>>(CF, WFH, WFL, BCAT, 0, QKVH, DD, QS);

    sample_scores_kernel<<<ROWS*HH/8, 256>>>(idxs);
    topk_kernel<<<BH, 256>>>();
    vmean_kernel<<<BH, 256>>>();
    ctx_bcast_kernel<<<ROWS*DD/512, 256>>>(CF);
    attn_scores_kernel<<<dim3(16, BH), 128>>>();
    attn_stats_kernel<<<BH, 256>>>();
    attn_pv_kernel<<<dim3(4, BH), 256, 55616>>>();
    attn_combine_kernel<<<BH, 256>>>(CF);

    gemm_hmma<0,0><<<gD, 256, SMEM>>>(CF, WFH+3*DW, WFL+3*DW, bo, T0, 0, DD, DD);
    ln_add_kernel<1><<<ROWS, 128>>>(x, T0, g1, be1, H1, H1F);

    gemm_hmma<1,2><<<gF, 256, SMEM>>>(H1F, WFH+4*DW, WFL+4*DW, b1, 0, GF, DD, FFD);
    gemm_hmma<0,0><<<gD, 256, SMEM>>>(GF, WFH+8*DW, WFL+8*DW, b2, T0, 0, FFD, DD);
    ln_add_kernel<0><<<ROWS, 128>>>(H1, T0, g2, be2, out, 0);
}

// round 13
// speedup vs baseline: 1.2322x; 1.2322x over previous
#include <cuda_runtime.h>
#include <cuda_fp16.h>
#include <math.h>
#include <stdint.h>

#define BB 4
#define LL 2048
#define DD 512
#define HH 8
#define DK 64
#define FFD 2048
#define NTOP 40
#define SK 40
#define BH (BB*HH)
#define ROWS (BB*LL)
#define QS 1536

__device__ float g_QKV[ROWS*QS];
__device__ float g_h1[ROWS*DD];
__device__ float g_t0[ROWS*DD];
__device__ float g_M[BH*LL];
__device__ float g_vmean[BH*DK];
__device__ int   g_top[BH*NTOP];
__device__ float g_bcat[QS];
__device__ float g_sc[BH*NTOP*LL];
__device__ float g_mx[BH*NTOP];
__device__ float g_inv[BH*NTOP];
__device__ float g_part[4*BH*NTOP*DK];
__device__ uint16_t g_Cf16[ROWS*DD];      // x-f16 for QKV GEMM, later ctx for Wo
__device__ uint16_t g_H1f16[ROWS*DD];
__device__ uint16_t g_Gf16[ROWS*FFD];
// weights: Wq/Wk/Wv hi@0..3DW + lo (2-term); Wo@3DW, W1@4DW, W2@8DW plain fp16 (1-term)
__device__ uint16_t g_Wf16h[12*DD*DD];
__device__ uint16_t g_Wf16l[3*DD*DD];

__device__ __forceinline__ uint32_t smem_u32(const void* p){
    uint32_t a; asm("{ .reg .u64 t; cvta.to.shared.u64 t, %1; cvt.u32.u64 %0, t; }":"=r"(a):"l"(p)); return a;
}
__device__ __forceinline__ void cpasync16(uint32_t dst, const void* src){
    asm volatile("cp.async.cg.shared.global [%0], [%1], 16;" :: "r"(dst), "l"(src));
}
__device__ __forceinline__ void ldsm4(uint32_t* r, uint32_t addr){
    asm volatile("ldmatrix.sync.aligned.m8n8.x4.shared.b16 {%0,%1,%2,%3}, [%4];"
        : "=r"(r[0]),"=r"(r[1]),"=r"(r[2]),"=r"(r[3]) : "r"(addr));
}
__device__ __forceinline__ void mma_fp(float* c, const uint32_t* a, const uint32_t* b){
    asm volatile("mma.sync.aligned.m16n8k16.row.col.f32.f16.f16.f32 "
        "{%0,%1,%2,%3}, {%4,%5,%6,%7}, {%8,%9}, {%0,%1,%2,%3};"
        : "+f"(c[0]),"+f"(c[1]),"+f"(c[2]),"+f"(c[3])
        : "r"(a[0]),"r"(a[1]),"r"(a[2]),"r"(a[3]),"r"(b[0]),"r"(b[1]));
}
__device__ __forceinline__ uint32_t packh(__half a, __half b){
    return (uint32_t)__half_as_ushort(a) | ((uint32_t)__half_as_ushort(b)<<16);
}
// branchless exact-GELU (A&S 7.1.26 erf approx, max abs err 1.5e-7)
__device__ __forceinline__ float gelu_fast(float v){
    float av = fabsf(v);
    float t = __fdividef(1.0f, fmaf(0.70710678118654752440f*0.3275911f, av, 1.0f));
    float poly = t*(0.254829592f + t*(-0.284496736f + t*(1.421413741f + t*(-1.453152027f + t*1.061405429f))));
    float e = __expf(-0.5f*v*v);
    float erfv = copysignf(1.0f - poly*e, v);
    return 0.5f*v*(1.0f + erfv);
}

// =====================================================================
// HMMA GEMM, fp16 with fp32 acc.
// TERMS=2: A x (B-hi + B-lo).  TERMS=1: A x B (plain fp16 weights).
// BM=BN=128, BK=32, 256 thr, 2 CTAs/SM, 3-stage cp.async pipeline.
// OUTMODE: 0 = fp32 C; 2 = fp16 C16. ACT=1: GELU.
// =====================================================================
template<int ACT, int OUTMODE, int TERMS>
__global__ void __launch_bounds__(256,2)
gemm_hmma(const uint16_t* __restrict__ A0,
          const uint16_t* __restrict__ B0, const uint16_t* __restrict__ B1,
          const float* __restrict__ bias, float* __restrict__ C,
          uint16_t* __restrict__ C16, int K, int ldc)
{
    extern __shared__ __align__(16) char sm[];
    const int t = threadIdx.x, lane = t&31, w = t>>5;
    const int wm = w>>2, wn = w&3;
    const int bm = blockIdx.y*128, bn = blockIdx.x*128;
    const int group = lane>>2, tig = lane&3;
    const uint32_t sbase = smem_u32(sm);
    const int NT = TERMS + 1;
    const int STAGE = NT*10240;

    float acc[4][4][4];
    #pragma unroll
    for (int i=0;i<4;i++)
        #pragma unroll
        for (int j=0;j<4;j++)
            #pragma unroll
            for (int r=0;r<4;r++) acc[i][j][r]=0.f;

    const uint16_t* srcs[3];
    srcs[0]=A0; srcs[1]=B0; srcs[2]=(TERMS==2)?B1:B0;
    const int nch = K>>5;
    #pragma unroll
    for (int pc=0; pc<2; pc++){
        const int k0 = pc<<5;
        const uint32_t dst0 = sbase + pc*STAGE;
        #pragma unroll
        for (int u=0; u<2*NT; u++){
            int q = t + u*256;
            int tile = q>>9, rem = q&511;
            int r = rem>>2, c = rem&3;
            const uint16_t* src = srcs[tile] + (size_t)(((tile<1)?bm:bn) + r)*K + k0 + c*8;
            cpasync16(dst0 + tile*10240 + r*80 + c*16, src);
        }
        asm volatile("cp.async.commit_group;");
    }
    const int brow_off = ((lane>>4)<<3) + (lane&7);
    const int bk_half  = (lane>>3)&1;
    int buf = 0;
    for (int ch=0; ch<nch; ch++){
        if (ch+2 < nch){
            const int k0 = (ch+2)<<5;
            int nb = buf+2; if (nb>=3) nb-=3;
            const uint32_t dst0 = sbase + nb*STAGE;
            #pragma unroll
            for (int u=0; u<2*NT; u++){
                int q = t + u*256;
                int tile = q>>9, rem = q&511;
                int r = rem>>2, c = rem&3;
                const uint16_t* src = srcs[tile] + (size_t)(((tile<1)?bm:bn) + r)*K + k0 + c*8;
                cpasync16(dst0 + tile*10240 + r*80 + c*16, src);
            }
            asm volatile("cp.async.commit_group;");
            asm volatile("cp.async.wait_group 2;");
        } else if (ch+1 < nch){
            asm volatile("cp.async.wait_group 1;");
        } else {
            asm volatile("cp.async.wait_group 0;");
        }
        __syncthreads();
        const uint32_t stg = sbase + buf*STAGE;
        #pragma unroll
        for (int kk=0; kk<2; kk++){
            uint32_t a_h[4][4];
            #pragma unroll
            for (int mt=0; mt<4; mt++){
                uint32_t ra = stg + (uint32_t)((wm*64 + mt*16 + (lane&15))*80 + (lane>>4)*16 + kk*32);
                ldsm4(a_h[mt], ra);
            }
            #pragma unroll
            for (int ntp=0; ntp<2; ntp++){
                uint32_t bh4[4];
                uint32_t rb = stg + 10240u +
                    (uint32_t)((wn*32 + ntp*16 + brow_off)*80 + bk_half*16 + kk*32);
                ldsm4(bh4, rb);
                if (TERMS==2){
                    uint32_t bl4[4];
                    ldsm4(bl4, rb + 10240u);
                    #pragma unroll
                    for (int mt=0; mt<4; mt++){
                        mma_fp(acc[mt][2*ntp+0], a_h[mt], &bh4[0]);
                        mma_fp(acc[mt][2*ntp+0], a_h[mt], &bl4[0]);
                        mma_fp(acc[mt][2*ntp+1], a_h[mt], &bh4[2]);
                        mma_fp(acc[mt][2*ntp+1], a_h[mt], &bl4[2]);
                    }
                } else {
                    #pragma unroll
                    for (int mt=0; mt<4; mt++){
                        mma_fp(acc[mt][2*ntp+0], a_h[mt], &bh4[0]);
                        mma_fp(acc[mt][2*ntp+1], a_h[mt], &bh4[2]);
                    }
                }
            }
        }
        __syncthreads();
        buf++; if (buf>=3) buf=0;
    }
    #pragma unroll
    for (int mt=0; mt<4; mt++){
        #pragma unroll
        for (int nt=0; nt<4; nt++){
            int r0  = bm + wm*64 + mt*16 + group;
            int col = bn + wn*32 + nt*8 + tig*2;
            float bb0 = bias[col], bb1 = bias[col+1];
            #pragma unroll
            for (int hh2=0; hh2<2; hh2++){
                int row = r0 + hh2*8;
                float v0 = acc[mt][nt][hh2*2+0] + bb0;
                float v1 = acc[mt][nt][hh2*2+1] + bb1;
                if (ACT==1){ v0 = gelu_fast(v0); v1 = gelu_fast(v1); }
                if (OUTMODE==0){
                    *(float2*)(C + (size_t)row*ldc + col) = make_float2(v0, v1);
                } else {
                    *(uint32_t*)(C16 + (size_t)row*ldc + col) =
                        packh(__float2half(v0), __float2half(v1));
                }
            }
        }
    }
}

__global__ void convert_wf16(const float* __restrict__ src,
                             uint16_t* __restrict__ hi, uint16_t* __restrict__ lo, int n4)
{
    int i = blockIdx.x*256 + threadIdx.x;
    if (i>=n4) return;
    float4 v = ((const float4*)src)[i];
    __half h0=__float2half(v.x), h1=__float2half(v.y), h2=__float2half(v.z), h3=__float2half(v.w);
    __half l0=__float2half(v.x-__half2float(h0)), l1=__float2half(v.y-__half2float(h1));
    __half l2=__float2half(v.z-__half2float(h2)), l3=__float2half(v.w-__half2float(h3));
    ((uint2*)hi)[i] = make_uint2(packh(h0,h1), packh(h2,h3));
    ((uint2*)lo)[i] = make_uint2(packh(l0,l1), packh(l2,l3));
}

__global__ void convert_f16(const float* __restrict__ src, uint16_t* __restrict__ dst, int n4)
{
    int i = blockIdx.x*256 + threadIdx.x;
    if (i>=n4) return;
    float4 v = ((const float4*)src)[i];
    ((uint2*)dst)[i] = make_uint2(packh(__float2half(v.x), __float2half(v.y)),
                                  packh(__float2half(v.z), __float2half(v.w)));
}

__global__ void bias_concat(const float* __restrict__ bq, const float* __restrict__ bk,
                            const float* __restrict__ bv)
{
    int t = blockIdx.x*256 + threadIdx.x;
    if (t>=QS) return;
    g_bcat[t] = (t<512)? bq[t] : (t<1024)? bk[t-512] : bv[t-1024];
}

__global__ void sample_scores_kernel(const int* __restrict__ idxs)
{
    int g = blockIdx.x*8 + (threadIdx.x>>5);
    int lane = threadIdx.x&31;
    int i = g&(LL-1), bh = g>>11, b = bh>>3, h = bh&7;
    const float2* qp = (const float2*)(g_QKV + (size_t)(b*LL+i)*QS + h*DK);
    float2 q = qp[lane];
    int myi0 = idxs[i*SK + lane];
    int myi1 = (lane<8)? idxs[i*SK + 32 + lane] : 0;
    const float* kbase = g_QKV + (size_t)b*LL*QS + 512 + h*DK;
    float mx = -INFINITY, sm = 0.f;
    #pragma unroll 4
    for (int j=0; j<SK; j++){
        int kidx = (j<32)? __shfl_sync(0xffffffffu, myi0, j)
                         : __shfl_sync(0xffffffffu, myi1, j-32);
        float2 kv = ((const float2*)(kbase + (size_t)kidx*QS))[lane];
        float s = q.x*kv.x + q.y*kv.y;
        #pragma unroll
        for (int off=16; off; off>>=1) s += __shfl_xor_sync(0xffffffffu, s, off);
        mx = fmaxf(mx, s); sm += s;
    }
    if (lane==0) g_M[bh*LL+i] = mx - sm*(1.0f/LL);
}

__global__ void topk_kernel()
{
    int bh = blockIdx.x, t = threadIdx.x;
    __shared__ uint32_t su[LL];
    __shared__ int hist[256];
    __shared__ int s_bucket, s_taken;
    __shared__ int tsum[256];
    __shared__ int s_ctr;

    for (int l=t; l<LL; l+=256){
        uint32_t s = __float_as_uint(g_M[bh*LL+l]);
        su[l] = (s & 0x80000000u)? ~s : (s | 0x80000000u);
    }
    if (t==0) s_ctr = 0;
    __syncthreads();

    uint32_t prefix = 0;
    int remaining = NTOP;
    #pragma unroll
    for (int round=0; round<4; round++){
        int shift = 24 - round*8;
        hist[t] = 0;
        __syncthreads();
        for (int l=t; l<LL; l+=256){
            uint32_t u = su[l];
            bool m = (round==0) || (((u ^ prefix) >> (shift+8)) == 0u);
            if (m) atomicAdd(&hist[(u>>shift)&255], 1);
        }
        __syncthreads();
        if (t < 32){
            int loc[8], run = 0;
            #pragma unroll
            for (int k=0; k<8; k++){
                int b = 255 - (t*8 + k);
                loc[k] = run;
                run += hist[b];
            }
            int lane_total = run;
            int scan = lane_total;
            #pragma unroll
            for (int off=1; off<32; off<<=1){
                int v = __shfl_up_sync(0xffffffffu, scan, off);
                if (t >= off) scan += v;
            }
            int excl = scan - lane_total;
            #pragma unroll
            for (int k=0; k<8; k++){
                int b = 255 - (t*8 + k);
                int cumAbove = excl + loc[k];
                if (cumAbove < remaining && remaining <= cumAbove + hist[b]){
                    s_bucket = b;
                    s_taken  = cumAbove;
                }
            }
        }
        __syncthreads();
        prefix |= ((uint32_t)s_bucket) << shift;
        remaining -= s_taken;
        __syncthreads();
    }
    const uint32_t T = prefix;
    const int r = remaining;
    const int cnt_gt = NTOP - r;

    int base = t*8, c = 0;
    #pragma unroll
    for (int k=0; k<8; k++) if (su[base+k] == T) c++;
    tsum[t] = c;
    __syncthreads();
    for (int off=1; off<256; off<<=1){
        int v = (t>=off)? tsum[t-off] : 0;
        __syncthreads();
        tsum[t] += v;
        __syncthreads();
    }
    int excl = tsum[t] - c;
    #pragma unroll
    for (int k=0; k<8; k++){
        uint32_t u = su[base+k];
        if (u > T){
            int pos = atomicAdd(&s_ctr, 1);
            g_top[bh*NTOP + pos] = base + k;
        } else if (u == T){
            if (excl < r) g_top[bh*NTOP + cnt_gt + excl] = base + k;
            excl++;
        }
    }
}

__global__ void vmean_kernel()
{
    int bh = blockIdx.x, b = bh>>3, h = bh&7;
    int t = threadIdx.x, d = t&63, r0 = t>>6;
    float s = 0.f;
    for (int l=r0; l<LL; l+=4) s += g_QKV[(size_t)(b*LL+l)*QS + 1024 + h*DK + d];
    __shared__ float red[256];
    red[t]=s; __syncthreads();
    if (t<64) g_vmean[bh*DK+t] = (red[t]+red[t+64]+red[t+128]+red[t+192])*(1.0f/LL);
}

__global__ void ctx_bcast_kernel(uint16_t* __restrict__ c16)
{
    int i = blockIdx.x*256 + threadIdx.x;
    int row = i>>8, c2 = (i&255)*2;
    int b = row>>11, h = c2>>6;
    const float* vm = g_vmean + (b*HH+h)*DK;
    *(uint32_t*)(c16 + (size_t)row*DD + c2) =
        packh(__float2half(vm[c2&63]), __float2half(vm[(c2&63)+1]));
}

__global__ void attn_scores_kernel()
{
    int kt = blockIdx.x, bh = blockIdx.y, b = bh>>3, h = bh&7;
    int t = threadIdx.x;
    __shared__ float sq[NTOP][64];
    __shared__ __align__(16) float Ks[128][68];
    __shared__ int tops[NTOP];
    if (t < NTOP) tops[t] = g_top[bh*NTOP + t];
    __syncthreads();
    const size_t qkv = (size_t)b*LL*QS;
    for (int idx=t; idx<NTOP*64; idx+=128){
        int qn = idx>>6, d = idx&63;
        sq[qn][d] = g_QKV[qkv + (size_t)tops[qn]*QS + h*DK + d];
    }
    #pragma unroll
    for (int u=0; u<16; u++){
        int f = t + u*128;
        int r = f>>4, c = (f&15)<<2;
        float4 kv = *(const float4*)(&g_QKV[qkv + (size_t)(kt*128+r)*QS + 512 + h*DK + c]);
        *(float4*)(&Ks[r][c]) = kv;
    }
    __syncthreads();
    float acc[NTOP];
    #pragma unroll
    for (int qn=0; qn<NTOP; qn++) acc[qn]=0.f;
    for (int k2=0; k2<32; k2++){
        float2 kv = *(const float2*)(&Ks[t][k2*2]);
        #pragma unroll
        for (int qn=0; qn<NTOP; qn++){
            float2 qv = *(const float2*)(&sq[qn][k2*2]);
            acc[qn] += kv.x*qv.x + kv.y*qv.y;
        }
    }
    #pragma unroll
    for (int qn=0; qn<NTOP; qn++)
        g_sc[((size_t)bh*NTOP + qn)*LL + kt*128 + t] = acc[qn];
}

__global__ void attn_stats_kernel()
{
    int bh = blockIdx.x;
    int w = threadIdx.x>>5, lane = threadIdx.x&31;
    for (int j=0; j<5; j++){
        int qn = w*5 + j;
        const float* sp = g_sc + ((size_t)bh*NTOP + qn)*LL;
        float mx = -INFINITY;
        for (int i=lane; i<LL; i+=32) mx = fmaxf(mx, sp[i]);
        #pragma unroll
        for (int off=16; off; off>>=1) mx = fmaxf(mx, __shfl_xor_sync(0xffffffffu, mx, off));
        float sum = 0.f;
        for (int i=lane; i<LL; i+=32) sum += expf(sp[i]-mx);
        #pragma unroll
        for (int off=16; off; off>>=1) sum += __shfl_xor_sync(0xffffffffu, sum, off);
        if (lane==0){ g_mx[bh*NTOP+qn]=mx; g_inv[bh*NTOP+qn]=1.0f/sum; }
    }
}

__global__ void attn_pv_kernel()
{
    extern __shared__ __align__(16) float psm[];
    float* Vs  = psm;
    float* P   = psm + 8704;
    float* smx = psm + 8704 + 5160;
    int ks = blockIdx.x, bh = blockIdx.y, b = bh>>3, h = bh&7;
    int t = threadIdx.x;
    if (t < NTOP) smx[t] = g_mx[bh*NTOP + t];
    __syncthreads();
    const size_t qkv = (size_t)b*LL*QS;
    int qg = t>>5, d2 = (t&31)*2;
    float acc[5][2];
    #pragma unroll
    for (int j=0;j<5;j++){ acc[j][0]=0.f; acc[j][1]=0.f; }
    for (int kt=0; kt<4; kt++){
        int ktg = ks*4 + kt;
        #pragma unroll
        for (int u=0; u<8; u++){
            int f = t + u*256;
            int r = f>>4, c = (f&15)<<2;
            float4 vv = *(const float4*)(&g_QKV[qkv + (size_t)(ktg*128+r)*QS + 1024 + h*DK + c]);
            *(float4*)(&Vs[r*68 + c]) = vv;
        }
        #pragma unroll
        for (int u=0; u<20; u++){
            int idx = t + u*256;
            int qn = idx>>7, row = idx&127;
            float s = g_sc[((size_t)bh*NTOP + qn)*LL + ktg*128 + row];
            P[qn*129 + row] = expf(s - smx[qn]);
        }
        __syncthreads();
        for (int row=0; row<128; row++){
            float2 vv = *(const float2*)(&Vs[row*68 + d2]);
            #pragma unroll
            for (int j=0; j<5; j++){
                float p = P[(qg*5+j)*129 + row];
                acc[j][0] += p*vv.x;
                acc[j][1] += p*vv.y;
            }
        }
        __syncthreads();
    }
    #pragma unroll
    for (int j=0; j<5; j++){
        int qn = qg*5 + j;
        float* dst = g_part + ((size_t)(ks*BH + bh)*NTOP + qn)*DK + d2;
        dst[0] = acc[j][0];
        dst[1] = acc[j][1];
    }
}

__global__ void attn_combine_kernel(uint16_t* __restrict__ c16)
{
    int bh = blockIdx.x, b = bh>>3, h = bh&7;
    int t = threadIdx.x;
    __shared__ int tops[NTOP];
    __shared__ float sinv[NTOP];
    if (t < NTOP){ tops[t] = g_top[bh*NTOP+t]; sinv[t] = g_inv[bh*NTOP+t]; }
    __syncthreads();
    for (int e=t; e<NTOP*DK/2; e+=256){
        int qn = e>>5, d2 = (e&31)*2;
        float s0=0.f, s1=0.f;
        #pragma unroll
        for (int ks=0; ks<4; ks++){
            const float* pp = g_part + ((size_t)(ks*BH + bh)*NTOP + qn)*DK + d2;
            s0 += pp[0]; s1 += pp[1];
        }
        s0 *= sinv[qn]; s1 *= sinv[qn];
        size_t o = (size_t)(b*LL + tops[qn])*DD + h*DK + d2;
        *(uint32_t*)(c16 + o) = packh(__float2half(s0), __float2half(s1));
    }
}

template<int F16OUT>
__global__ void ln_add_kernel(const float* __restrict__ X, const float* __restrict__ Y,
                              const float* __restrict__ gg, const float* __restrict__ be,
                              float* __restrict__ out, uint16_t* __restrict__ o16)
{
    int row = blockIdx.x, t = threadIdx.x;
    float4 a = ((const float4*)(X + (size_t)row*DD))[t];
    float4 bq = ((const float4*)(Y + (size_t)row*DD))[t];
    float4 v = make_float4(a.x+bq.x, a.y+bq.y, a.z+bq.z, a.w+bq.w);
    float s = v.x+v.y+v.z+v.w;
    float ss = v.x*v.x+v.y*v.y+v.z*v.z+v.w*v.w;
    __shared__ float rs[128], rq[128];
    rs[t]=s; rq[t]=ss; __syncthreads();
    for (int k=64; k; k>>=1){ if (t<k){ rs[t]+=rs[t+k]; rq[t]+=rq[t+k]; } __syncthreads(); }
    float mean = rs[0]*(1.0f/DD);
    float var  = rq[0]*(1.0f/DD) - mean*mean;
    float rstd = rsqrtf(var + 1e-5f);
    float4 g4 = ((const float4*)gg)[t], b4 = ((const float4*)be)[t];
    float4 o;
    o.x=(v.x-mean)*rstd*g4.x+b4.x; o.y=(v.y-mean)*rstd*g4.y+b4.y;
    o.z=(v.z-mean)*rstd*g4.z+b4.z; o.w=(v.w-mean)*rstd*g4.w+b4.w;
    ((float4*)(out + (size_t)row*DD))[t] = o;
    if (F16OUT){
        ((uint2*)(o16 + (size_t)row*DD))[t] = make_uint2(
            packh(__float2half(o.x), __float2half(o.y)),
            packh(__float2half(o.z), __float2half(o.w)));
    }
}

extern "C" void kernel_launch(void* const* d_in, const int* in_sizes, int n_in,
                              void* d_out, int out_size)
{
    const float* x    = (const float*)d_in[0];
    const int*   idxs = (const int*)  d_in[1];
    const float* Wq = (const float*)d_in[2];  const float* bq = (const float*)d_in[3];
    const float* Wk = (const float*)d_in[4];  const float* bk = (const float*)d_in[5];
    const float* Wv = (const float*)d_in[6];  const float* bv = (const float*)d_in[7];
    const float* Wo = (const float*)d_in[8];  const float* bo = (const float*)d_in[9];
    const float* W1 = (const float*)d_in[10]; const float* b1 = (const float*)d_in[11];
    const float* W2 = (const float*)d_in[12]; const float* b2 = (const float*)d_in[13];
    const float* g1 = (const float*)d_in[14]; const float* be1 = (const float*)d_in[15];
    const float* g2 = (const float*)d_in[16]; const float* be2 = (const float*)d_in[17];
    float* out = (float*)d_out;

    float *QKV,*H1,*T0,*BCAT;
    uint16_t *CF,*H1F,*GF,*WFH,*WFL;
    cudaGetSymbolAddress((void**)&QKV, g_QKV);
    cudaGetSymbolAddress((void**)&H1, g_h1);   cudaGetSymbolAddress((void**)&T0, g_t0);
    cudaGetSymbolAddress((void**)&BCAT, g_bcat);
    cudaGetSymbolAddress((void**)&CF, g_Cf16); cudaGetSymbolAddress((void**)&H1F, g_H1f16);
    cudaGetSymbolAddress((void**)&GF, g_Gf16);
    cudaGetSymbolAddress((void**)&WFH, g_Wf16h); cudaGetSymbolAddress((void**)&WFL, g_Wf16l);

    const int SMEM2 = 92160, SMEM1 = 61440;
    cudaFuncSetAttribute(gemm_hmma<0,0,2>, cudaFuncAttributeMaxDynamicSharedMemorySize, SMEM2);
    cudaFuncSetAttribute(gemm_hmma<0,0,1>, cudaFuncAttributeMaxDynamicSharedMemorySize, SMEM1);
    cudaFuncSetAttribute(gemm_hmma<1,2,1>, cudaFuncAttributeMaxDynamicSharedMemorySize, SMEM1);
    cudaFuncSetAttribute(attn_pv_kernel, cudaFuncAttributeMaxDynamicSharedMemorySize, 55616);

    const int DW = DD*DD;
    // 2-term QKV weights (hi/lo)
    convert_wf16<<<DW/1024, 256>>>(Wq, WFH+0*DW, WFL+0*DW, DW/4);
    convert_wf16<<<DW/1024, 256>>>(Wk, WFH+1*DW, WFL+1*DW, DW/4);
    convert_wf16<<<DW/1024, 256>>>(Wv, WFH+2*DW, WFL+2*DW, DW/4);
    // 1-term weights (plain fp16)
    convert_f16<<<DW/1024, 256>>>(Wo, WFH+3*DW, DW/4);
    convert_f16<<<DW*4/1024, 256>>>(W1, WFH+4*DW, DW);
    convert_f16<<<DW*4/1024, 256>>>(W2, WFH+8*DW, DW);
    convert_f16<<<ROWS*DD/1024, 256>>>(x, CF, ROWS*DD/4);
    bias_concat<<<QS/256, 256>>>(bq, bk, bv);

    dim3 gQKV(QS/128, ROWS/128), gD(DD/128, ROWS/128), gF(FFD/128, ROWS/128);
    gemm_hmma<0,0,2><<<gQKV, 256, SMEM2>>>(CF, WFH, WFL, BCAT, QKV, 0, DD, QS);

    sample_scores_kernel<<<ROWS*HH/8, 256>>>(idxs);
    topk_kernel<<<BH, 256>>>();
    vmean_kernel<<<BH, 256>>>();
    ctx_bcast_kernel<<<ROWS*DD/512, 256>>>(CF);
    attn_scores_kernel<<<dim3(16, BH), 128>>>();
    attn_stats_kernel<<<BH, 256>>>();
    attn_pv_kernel<<<dim3(4, BH), 256, 55616>>>();
    attn_combine_kernel<<<BH, 256>>>(CF);

    gemm_hmma<0,0,1><<<gD, 256, SMEM1>>>(CF, WFH+3*DW, 0, bo, T0, 0, DD, DD);
    ln_add_kernel<1><<<ROWS, 128>>>(x, T0, g1, be1, H1, H1F);

    gemm_hmma<1,2,1><<<gF, 256, SMEM1>>>(H1F, WFH+4*DW, 0, b1, 0, GF, DD, FFD);
    gemm_hmma<0,0,1><<<gD, 256, SMEM1>>>(GF, WFH+8*DW, 0, b2, T0, 0, FFD, DD);
    ln_add_kernel<0><<<ROWS, 128>>>(H1, T0, g2, be2, out, 0);
}

// round 14
// speedup vs baseline: 1.3257x; 1.0758x over previous
#include <cuda_runtime.h>
#include <cuda_fp16.h>
#include <math.h>
#include <stdint.h>

#define BB 4
#define LL 2048
#define DD 512
#define HH 8
#define DK 64
#define FFD 2048
#define NTOP 40
#define SK 40
#define BH (BB*HH)
#define ROWS (BB*LL)
#define QS 1536

__device__ float g_QKV[ROWS*QS];
__device__ float g_h1[ROWS*DD];
__device__ float g_t0[ROWS*DD];
__device__ float g_M[BH*LL];
__device__ float g_vmean[BH*DK];
__device__ int   g_top[BH*NTOP];
__device__ float g_bcat[QS];
__device__ float g_sc[BH*NTOP*LL];
__device__ float g_mx[BH*NTOP];
__device__ float g_inv[BH*NTOP];
__device__ float g_part[4*BH*NTOP*DK];
__device__ uint16_t g_Cf16[ROWS*DD];      // x-f16 for QKV GEMM, later ctx for Wo
__device__ uint16_t g_H1f16[ROWS*DD];
__device__ uint16_t g_Gf16[ROWS*FFD];
// plain fp16 weights: Wqkv@0 (3DW concat), Wo@3DW, W1@4DW, W2@8DW
__device__ uint16_t g_Wf16h[12*DD*DD];

__device__ __forceinline__ uint32_t smem_u32(const void* p){
    uint32_t a; asm("{ .reg .u64 t; cvta.to.shared.u64 t, %1; cvt.u32.u64 %0, t; }":"=r"(a):"l"(p)); return a;
}
__device__ __forceinline__ void cpasync16(uint32_t dst, const void* src){
    asm volatile("cp.async.cg.shared.global [%0], [%1], 16;" :: "r"(dst), "l"(src));
}
__device__ __forceinline__ void ldsm4(uint32_t* r, uint32_t addr){
    asm volatile("ldmatrix.sync.aligned.m8n8.x4.shared.b16 {%0,%1,%2,%3}, [%4];"
        : "=r"(r[0]),"=r"(r[1]),"=r"(r[2]),"=r"(r[3]) : "r"(addr));
}
__device__ __forceinline__ void mma_fp(float* c, const uint32_t* a, const uint32_t* b){
    asm volatile("mma.sync.aligned.m16n8k16.row.col.f32.f16.f16.f32 "
        "{%0,%1,%2,%3}, {%4,%5,%6,%7}, {%8,%9}, {%0,%1,%2,%3};"
        : "+f"(c[0]),"+f"(c[1]),"+f"(c[2]),"+f"(c[3])
        : "r"(a[0]),"r"(a[1]),"r"(a[2]),"r"(a[3]),"r"(b[0]),"r"(b[1]));
}
__device__ __forceinline__ uint32_t packh(__half a, __half b){
    return (uint32_t)__half_as_ushort(a) | ((uint32_t)__half_as_ushort(b)<<16);
}
// branchless exact-GELU (A&S 7.1.26 erf approx, max abs err 1.5e-7)
__device__ __forceinline__ float gelu_fast(float v){
    float av = fabsf(v);
    float t = __fdividef(1.0f, fmaf(0.70710678118654752440f*0.3275911f, av, 1.0f));
    float poly = t*(0.254829592f + t*(-0.284496736f + t*(1.421413741f + t*(-1.453152027f + t*1.061405429f))));
    float e = __expf(-0.5f*v*v);
    float erfv = copysignf(1.0f - poly*e, v);
    return 0.5f*v*(1.0f + erfv);
}

// =====================================================================
// HMMA GEMM: plain fp16 A x fp16 B, fp32 acc. BM=BN=128, BK=32, 256 thr,
// 2 CTAs/SM, 3-stage cp.async pipeline (stage = A|B = 20480B, x3 = 61440B).
// OUTMODE: 0 = fp32 C; 2 = fp16 C16. ACT=1: GELU.
// =====================================================================
template<int ACT, int OUTMODE>
__global__ void __launch_bounds__(256,2)
gemm_hmma(const uint16_t* __restrict__ A0, const uint16_t* __restrict__ B0,
          const float* __restrict__ bias, float* __restrict__ C,
          uint16_t* __restrict__ C16, int K, int ldc)
{
    extern __shared__ __align__(16) char sm[];
    const int t = threadIdx.x, lane = t&31, w = t>>5;
    const int wm = w>>2, wn = w&3;
    const int bm = blockIdx.y*128, bn = blockIdx.x*128;
    const int group = lane>>2, tig = lane&3;
    const uint32_t sbase = smem_u32(sm);
    const int STAGE = 20480;

    float acc[4][4][4];
    #pragma unroll
    for (int i=0;i<4;i++)
        #pragma unroll
        for (int j=0;j<4;j++)
            #pragma unroll
            for (int r=0;r<4;r++) acc[i][j][r]=0.f;

    const uint16_t* srcs[2] = {A0, B0};
    const int nch = K>>5;
    #pragma unroll
    for (int pc=0; pc<2; pc++){
        const int k0 = pc<<5;
        const uint32_t dst0 = sbase + pc*STAGE;
        #pragma unroll
        for (int u=0; u<4; u++){
            int q = t + u*256;
            int tile = q>>9, rem = q&511;
            int r = rem>>2, c = rem&3;
            const uint16_t* src = srcs[tile] + (size_t)(((tile<1)?bm:bn) + r)*K + k0 + c*8;
            cpasync16(dst0 + tile*10240 + r*80 + c*16, src);
        }
        asm volatile("cp.async.commit_group;");
    }
    const int brow_off = ((lane>>4)<<3) + (lane&7);
    const int bk_half  = (lane>>3)&1;
    int buf = 0;
    for (int ch=0; ch<nch; ch++){
        if (ch+2 < nch){
            const int k0 = (ch+2)<<5;
            int nb = buf+2; if (nb>=3) nb-=3;
            const uint32_t dst0 = sbase + nb*STAGE;
            #pragma unroll
            for (int u=0; u<4; u++){
                int q = t + u*256;
                int tile = q>>9, rem = q&511;
                int r = rem>>2, c = rem&3;
                const uint16_t* src = srcs[tile] + (size_t)(((tile<1)?bm:bn) + r)*K + k0 + c*8;
                cpasync16(dst0 + tile*10240 + r*80 + c*16, src);
            }
            asm volatile("cp.async.commit_group;");
            asm volatile("cp.async.wait_group 2;");
        } else if (ch+1 < nch){
            asm volatile("cp.async.wait_group 1;");
        } else {
            asm volatile("cp.async.wait_group 0;");
        }
        __syncthreads();
        const uint32_t stg = sbase + buf*STAGE;
        #pragma unroll
        for (int kk=0; kk<2; kk++){
            uint32_t a_h[4][4];
            #pragma unroll
            for (int mt=0; mt<4; mt++){
                uint32_t ra = stg + (uint32_t)((wm*64 + mt*16 + (lane&15))*80 + (lane>>4)*16 + kk*32);
                ldsm4(a_h[mt], ra);
            }
            #pragma unroll
            for (int ntp=0; ntp<2; ntp++){
                uint32_t bh4[4];
                uint32_t rb = stg + 10240u +
                    (uint32_t)((wn*32 + ntp*16 + brow_off)*80 + bk_half*16 + kk*32);
                ldsm4(bh4, rb);
                #pragma unroll
                for (int mt=0; mt<4; mt++){
                    mma_fp(acc[mt][2*ntp+0], a_h[mt], &bh4[0]);
                    mma_fp(acc[mt][2*ntp+1], a_h[mt], &bh4[2]);
                }
            }
        }
        __syncthreads();
        buf++; if (buf>=3) buf=0;
    }
    #pragma unroll
    for (int mt=0; mt<4; mt++){
        #pragma unroll
        for (int nt=0; nt<4; nt++){
            int r0  = bm + wm*64 + mt*16 + group;
            int col = bn + wn*32 + nt*8 + tig*2;
            float bb0 = bias[col], bb1 = bias[col+1];
            #pragma unroll
            for (int hh2=0; hh2<2; hh2++){
                int row = r0 + hh2*8;
                float v0 = acc[mt][nt][hh2*2+0] + bb0;
                float v1 = acc[mt][nt][hh2*2+1] + bb1;
                if (ACT==1){ v0 = gelu_fast(v0); v1 = gelu_fast(v1); }
                if (OUTMODE==0){
                    *(float2*)(C + (size_t)row*ldc + col) = make_float2(v0, v1);
                } else {
                    *(uint32_t*)(C16 + (size_t)row*ldc + col) =
                        packh(__float2half(v0), __float2half(v1));
                }
            }
        }
    }
}

__global__ void convert_f16(const float* __restrict__ src, uint16_t* __restrict__ dst, int n4)
{
    int i = blockIdx.x*256 + threadIdx.x;
    if (i>=n4) return;
    float4 v = ((const float4*)src)[i];
    ((uint2*)dst)[i] = make_uint2(packh(__float2half(v.x), __float2half(v.y)),
                                  packh(__float2half(v.z), __float2half(v.w)));
}

__global__ void bias_concat(const float* __restrict__ bq, const float* __restrict__ bk,
                            const float* __restrict__ bv)
{
    int t = blockIdx.x*256 + threadIdx.x;
    if (t>=QS) return;
    g_bcat[t] = (t<512)? bq[t] : (t<1024)? bk[t-512] : bv[t-1024];
}

__global__ void sample_scores_kernel(const int* __restrict__ idxs)
{
    int g = blockIdx.x*8 + (threadIdx.x>>5);
    int lane = threadIdx.x&31;
    int i = g&(LL-1), bh = g>>11, b = bh>>3, h = bh&7;
    const float2* qp = (const float2*)(g_QKV + (size_t)(b*LL+i)*QS + h*DK);
    float2 q = qp[lane];
    int myi0 = idxs[i*SK + lane];
    int myi1 = (lane<8)? idxs[i*SK + 32 + lane] : 0;
    const float* kbase = g_QKV + (size_t)b*LL*QS + 512 + h*DK;
    float mx = -INFINITY, sm = 0.f;
    #pragma unroll 4
    for (int j=0; j<SK; j++){
        int kidx = (j<32)? __shfl_sync(0xffffffffu, myi0, j)
                         : __shfl_sync(0xffffffffu, myi1, j-32);
        float2 kv = ((const float2*)(kbase + (size_t)kidx*QS))[lane];
        float s = q.x*kv.x + q.y*kv.y;
        #pragma unroll
        for (int off=16; off; off>>=1) s += __shfl_xor_sync(0xffffffffu, s, off);
        mx = fmaxf(mx, s); sm += s;
    }
    if (lane==0) g_M[bh*LL+i] = mx - sm*(1.0f/LL);
}

__global__ void topk_kernel()
{
    int bh = blockIdx.x, t = threadIdx.x;
    __shared__ uint32_t su[LL];
    __shared__ int hist[256];
    __shared__ int s_bucket, s_taken;
    __shared__ int tsum[256];
    __shared__ int s_ctr;

    for (int l=t; l<LL; l+=256){
        uint32_t s = __float_as_uint(g_M[bh*LL+l]);
        su[l] = (s & 0x80000000u)? ~s : (s | 0x80000000u);
    }
    if (t==0) s_ctr = 0;
    __syncthreads();

    uint32_t prefix = 0;
    int remaining = NTOP;
    #pragma unroll
    for (int round=0; round<4; round++){
        int shift = 24 - round*8;
        hist[t] = 0;
        __syncthreads();
        for (int l=t; l<LL; l+=256){
            uint32_t u = su[l];
            bool m = (round==0) || (((u ^ prefix) >> (shift+8)) == 0u);
            if (m) atomicAdd(&hist[(u>>shift)&255], 1);
        }
        __syncthreads();
        if (t < 32){
            int loc[8], run = 0;
            #pragma unroll
            for (int k=0; k<8; k++){
                int b = 255 - (t*8 + k);
                loc[k] = run;
                run += hist[b];
            }
            int lane_total = run;
            int scan = lane_total;
            #pragma unroll
            for (int off=1; off<32; off<<=1){
                int v = __shfl_up_sync(0xffffffffu, scan, off);
                if (t >= off) scan += v;
            }
            int excl = scan - lane_total;
            #pragma unroll
            for (int k=0; k<8; k++){
                int b = 255 - (t*8 + k);
                int cumAbove = excl + loc[k];
                if (cumAbove < remaining && remaining <= cumAbove + hist[b]){
                    s_bucket = b;
                    s_taken  = cumAbove;
                }
            }
        }
        __syncthreads();
        prefix |= ((uint32_t)s_bucket) << shift;
        remaining -= s_taken;
        __syncthreads();
    }
    const uint32_t T = prefix;
    const int r = remaining;
    const int cnt_gt = NTOP - r;

    int base = t*8, c = 0;
    #pragma unroll
    for (int k=0; k<8; k++) if (su[base+k] == T) c++;
    tsum[t] = c;
    __syncthreads();
    for (int off=1; off<256; off<<=1){
        int v = (t>=off)? tsum[t-off] : 0;
        __syncthreads();
        tsum[t] += v;
        __syncthreads();
    }
    int excl = tsum[t] - c;
    #pragma unroll
    for (int k=0; k<8; k++){
        uint32_t u = su[base+k];
        if (u > T){
            int pos = atomicAdd(&s_ctr, 1);
            g_top[bh*NTOP + pos] = base + k;
        } else if (u == T){
            if (excl < r) g_top[bh*NTOP + cnt_gt + excl] = base + k;
            excl++;
        }
    }
}

__global__ void vmean_kernel()
{
    int bh = blockIdx.x, b = bh>>3, h = bh&7;
    int t = threadIdx.x, d = t&63, r0 = t>>6;
    float s = 0.f;
    for (int l=r0; l<LL; l+=4) s += g_QKV[(size_t)(b*LL+l)*QS + 1024 + h*DK + d];
    __shared__ float red[256];
    red[t]=s; __syncthreads();
    if (t<64) g_vmean[bh*DK+t] = (red[t]+red[t+64]+red[t+128]+red[t+192])*(1.0f/LL);
}

__global__ void ctx_bcast_kernel(uint16_t* __restrict__ c16)
{
    int i = blockIdx.x*256 + threadIdx.x;
    int row = i>>8, c2 = (i&255)*2;
    int b = row>>11, h = c2>>6;
    const float* vm = g_vmean + (b*HH+h)*DK;
    *(uint32_t*)(c16 + (size_t)row*DD + c2) =
        packh(__float2half(vm[c2&63]), __float2half(vm[(c2&63)+1]));
}

__global__ void attn_scores_kernel()
{
    int kt = blockIdx.x, bh = blockIdx.y, b = bh>>3, h = bh&7;
    int t = threadIdx.x;
    __shared__ float sq[NTOP][64];
    __shared__ __align__(16) float Ks[128][68];
    __shared__ int tops[NTOP];
    if (t < NTOP) tops[t] = g_top[bh*NTOP + t];
    __syncthreads();
    const size_t qkv = (size_t)b*LL*QS;
    for (int idx=t; idx<NTOP*64; idx+=128){
        int qn = idx>>6, d = idx&63;
        sq[qn][d] = g_QKV[qkv + (size_t)tops[qn]*QS + h*DK + d];
    }
    #pragma unroll
    for (int u=0; u<16; u++){
        int f = t + u*128;
        int r = f>>4, c = (f&15)<<2;
        float4 kv = *(const float4*)(&g_QKV[qkv + (size_t)(kt*128+r)*QS + 512 + h*DK + c]);
        *(float4*)(&Ks[r][c]) = kv;
    }
    __syncthreads();
    float acc[NTOP];
    #pragma unroll
    for (int qn=0; qn<NTOP; qn++) acc[qn]=0.f;
    for (int k2=0; k2<32; k2++){
        float2 kv = *(const float2*)(&Ks[t][k2*2]);
        #pragma unroll
        for (int qn=0; qn<NTOP; qn++){
            float2 qv = *(const float2*)(&sq[qn][k2*2]);
            acc[qn] += kv.x*qv.x + kv.y*qv.y;
        }
    }
    #pragma unroll
    for (int qn=0; qn<NTOP; qn++)
        g_sc[((size_t)bh*NTOP + qn)*LL + kt*128 + t] = acc[qn];
}

__global__ void attn_stats_kernel()
{
    int bh = blockIdx.x;
    int w = threadIdx.x>>5, lane = threadIdx.x&31;
    for (int j=0; j<5; j++){
        int qn = w*5 + j;
        const float* sp = g_sc + ((size_t)bh*NTOP + qn)*LL;
        float mx = -INFINITY;
        for (int i=lane; i<LL; i+=32) mx = fmaxf(mx, sp[i]);
        #pragma unroll
        for (int off=16; off; off>>=1) mx = fmaxf(mx, __shfl_xor_sync(0xffffffffu, mx, off));
        float sum = 0.f;
        for (int i=lane; i<LL; i+=32) sum += expf(sp[i]-mx);
        #pragma unroll
        for (int off=16; off; off>>=1) sum += __shfl_xor_sync(0xffffffffu, sum, off);
        if (lane==0){ g_mx[bh*NTOP+qn]=mx; g_inv[bh*NTOP+qn]=1.0f/sum; }
    }
}

__global__ void attn_pv_kernel()
{
    extern __shared__ __align__(16) float psm[];
    float* Vs  = psm;
    float* P   = psm + 8704;
    float* smx = psm + 8704 + 5160;
    int ks = blockIdx.x, bh = blockIdx.y, b = bh>>3, h = bh&7;
    int t = threadIdx.x;
    if (t < NTOP) smx[t] = g_mx[bh*NTOP + t];
    __syncthreads();
    const size_t qkv = (size_t)b*LL*QS;
    int qg = t>>5, d2 = (t&31)*2;
    float acc[5][2];
    #pragma unroll
    for (int j=0;j<5;j++){ acc[j][0]=0.f; acc[j][1]=0.f; }
    for (int kt=0; kt<4; kt++){
        int ktg = ks*4 + kt;
        #pragma unroll
        for (int u=0; u<8; u++){
            int f = t + u*256;
            int r = f>>4, c = (f&15)<<2;
            float4 vv = *(const float4*)(&g_QKV[qkv + (size_t)(ktg*128+r)*QS + 1024 + h*DK + c]);
            *(float4*)(&Vs[r*68 + c]) = vv;
        }
        #pragma unroll
        for (int u=0; u<20; u++){
            int idx = t + u*256;
            int qn = idx>>7, row = idx&127;
            float s = g_sc[((size_t)bh*NTOP + qn)*LL + ktg*128 + row];
            P[qn*129 + row] = expf(s - smx[qn]);
        }
        __syncthreads();
        for (int row=0; row<128; row++){
            float2 vv = *(const float2*)(&Vs[row*68 + d2]);
            #pragma unroll
            for (int j=0; j<5; j++){
                float p = P[(qg*5+j)*129 + row];
                acc[j][0] += p*vv.x;
                acc[j][1] += p*vv.y;
            }
        }
        __syncthreads();
    }
    #pragma unroll
    for (int j=0; j<5; j++){
        int qn = qg*5 + j;
        float* dst = g_part + ((size_t)(ks*BH + bh)*NTOP + qn)*DK + d2;
        dst[0] = acc[j][0];
        dst[1] = acc[j][1];
    }
}

__global__ void attn_combine_kernel(uint16_t* __restrict__ c16)
{
    int bh = blockIdx.x, b = bh>>3, h = bh&7;
    int t = threadIdx.x;
    __shared__ int tops[NTOP];
    __shared__ float sinv[NTOP];
    if (t < NTOP){ tops[t] = g_top[bh*NTOP+t]; sinv[t] = g_inv[bh*NTOP+t]; }
    __syncthreads();
    for (int e=t; e<NTOP*DK/2; e+=256){
        int qn = e>>5, d2 = (e&31)*2;
        float s0=0.f, s1=0.f;
        #pragma unroll
        for (int ks=0; ks<4; ks++){
            const float* pp = g_part + ((size_t)(ks*BH + bh)*NTOP + qn)*DK + d2;
            s0 += pp[0]; s1 += pp[1];
        }
        s0 *= sinv[qn]; s1 *= sinv[qn];
        size_t o = (size_t)(b*LL + tops[qn])*DD + h*DK + d2;
        *(uint32_t*)(c16 + o) = packh(__float2half(s0), __float2half(s1));
    }
}

template<int F16OUT>
__global__ void ln_add_kernel(const float* __restrict__ X, const float* __restrict__ Y,
                              const float* __restrict__ gg, const float* __restrict__ be,
                              float* __restrict__ out, uint16_t* __restrict__ o16)
{
    int row = blockIdx.x, t = threadIdx.x;
    float4 a = ((const float4*)(X + (size_t)row*DD))[t];
    float4 bq = ((const float4*)(Y + (size_t)row*DD))[t];
    float4 v = make_float4(a.x+bq.x, a.y+bq.y, a.z+bq.z, a.w+bq.w);
    float s = v.x+v.y+v.z+v.w;
    float ss = v.x*v.x+v.y*v.y+v.z*v.z+v.w*v.w;
    __shared__ float rs[128], rq[128];
    rs[t]=s; rq[t]=ss; __syncthreads();
    for (int k=64; k; k>>=1){ if (t<k){ rs[t]+=rs[t+k]; rq[t]+=rq[t+k]; } __syncthreads(); }
    float mean = rs[0]*(1.0f/DD);
    float var  = rq[0]*(1.0f/DD) - mean*mean;
    float rstd = rsqrtf(var + 1e-5f);
    float4 g4 = ((const float4*)gg)[t], b4 = ((const float4*)be)[t];
    float4 o;
    o.x=(v.x-mean)*rstd*g4.x+b4.x; o.y=(v.y-mean)*rstd*g4.y+b4.y;
    o.z=(v.z-mean)*rstd*g4.z+b4.z; o.w=(v.w-mean)*rstd*g4.w+b4.w;
    ((float4*)(out + (size_t)row*DD))[t] = o;
    if (F16OUT){
        ((uint2*)(o16 + (size_t)row*DD))[t] = make_uint2(
            packh(__float2half(o.x), __float2half(o.y)),
            packh(__float2half(o.z), __float2half(o.w)));
    }
}

extern "C" void kernel_launch(void* const* d_in, const int* in_sizes, int n_in,
                              void* d_out, int out_size)
{
    const float* x    = (const float*)d_in[0];
    const int*   idxs = (const int*)  d_in[1];
    const float* Wq = (const float*)d_in[2];  const float* bq = (const float*)d_in[3];
    const float* Wk = (const float*)d_in[4];  const float* bk = (const float*)d_in[5];
    const float* Wv = (const float*)d_in[6];  const float* bv = (const float*)d_in[7];
    const float* Wo = (const float*)d_in[8];  const float* bo = (const float*)d_in[9];
    const float* W1 = (const float*)d_in[10]; const float* b1 = (const float*)d_in[11];
    const float* W2 = (const float*)d_in[12]; const float* b2 = (const float*)d_in[13];
    const float* g1 = (const float*)d_in[14]; const float* be1 = (const float*)d_in[15];
    const float* g2 = (const float*)d_in[16]; const float* be2 = (const float*)d_in[17];
    float* out = (float*)d_out;

    float *QKV,*H1,*T0,*BCAT;
    uint16_t *CF,*H1F,*GF,*WFH;
    cudaGetSymbolAddress((void**)&QKV, g_QKV);
    cudaGetSymbolAddress((void**)&H1, g_h1);   cudaGetSymbolAddress((void**)&T0, g_t0);
    cudaGetSymbolAddress((void**)&BCAT, g_bcat);
    cudaGetSymbolAddress((void**)&CF, g_Cf16); cudaGetSymbolAddress((void**)&H1F, g_H1f16);
    cudaGetSymbolAddress((void**)&GF, g_Gf16);
    cudaGetSymbolAddress((void**)&WFH, g_Wf16h);

    const int SMEM = 61440;
    cudaFuncSetAttribute(gemm_hmma<0,0>, cudaFuncAttributeMaxDynamicSharedMemorySize, SMEM);
    cudaFuncSetAttribute(gemm_hmma<1,2>, cudaFuncAttributeMaxDynamicSharedMemorySize, SMEM);
    cudaFuncSetAttribute(attn_pv_kernel, cudaFuncAttributeMaxDynamicSharedMemorySize, 55616);

    const int DW = DD*DD;
    convert_f16<<<DW/1024, 256>>>(Wq, WFH+0*DW, DW/4);
    convert_f16<<<DW/1024, 256>>>(Wk, WFH+1*DW, DW/4);
    convert_f16<<<DW/1024, 256>>>(Wv, WFH+2*DW, DW/4);
    convert_f16<<<DW/1024, 256>>>(Wo, WFH+3*DW, DW/4);
    convert_f16<<<DW*4/1024, 256>>>(W1, WFH+4*DW, DW);
    convert_f16<<<DW*4/1024, 256>>>(W2, WFH+8*DW, DW);
    convert_f16<<<ROWS*DD/1024, 256>>>(x, CF, ROWS*DD/4);
    bias_concat<<<QS/256, 256>>>(bq, bk, bv);

    dim3 gQKV(QS/128, ROWS/128), gD(DD/128, ROWS/128), gF(FFD/128, ROWS/128);
    gemm_hmma<0,0><<<gQKV, 256, SMEM>>>(CF, WFH, BCAT, QKV, 0, DD, QS);

    sample_scores_kernel<<<ROWS*HH/8, 256>>>(idxs);
    topk_kernel<<<BH, 256>>>();
    vmean_kernel<<<BH, 256>>>();
    ctx_bcast_kernel<<<ROWS*DD/512, 256>>>(CF);
    attn_scores_kernel<<<dim3(16, BH), 128>>>();
    attn_stats_kernel<<<BH, 256>>>();
    attn_pv_kernel<<<dim3(4, BH), 256, 55616>>>();
    attn_combine_kernel<<<BH, 256>>>(CF);

    gemm_hmma<0,0><<<gD, 256, SMEM>>>(CF, WFH+3*DW, bo, T0, 0, DD, DD);
    ln_add_kernel<1><<<ROWS, 128>>>(x, T0, g1, be1, H1, H1F);

    gemm_hmma<1,2><<<gF, 256, SMEM>>>(H1F, WFH+4*DW, b1, 0, GF, DD, FFD);
    gemm_hmma<0,0><<<gD, 256, SMEM>>>(GF, WFH+8*DW, b2, T0, 0, FFD, DD);
    ln_add_kernel<0><<<ROWS, 128>>>(H1, T0, g2, be2, out, 0);
}

// round 15
// speedup vs baseline: 1.3373x; 1.0087x over previous
#include <cuda_runtime.h>
#include <cuda_fp16.h>
#include <math.h>
#include <stdint.h>

#define BB 4
#define LL 2048
#define DD 512
#define HH 8
#define DK 64
#define FFD 2048
#define NTOP 40
#define SK 40
#define BH (BB*HH)
#define ROWS (BB*LL)
#define QS 1536
#define DW (DD*DD)

__device__ float g_QKV[ROWS*QS];
__device__ uint16_t g_Kh[ROWS*DD];        // fp16 mirror of K section (for sample gather)
__device__ float g_h1[ROWS*DD];
__device__ float g_t0[ROWS*DD];
__device__ float g_M[BH*LL];
__device__ float g_vmean[BH*DK];
__device__ int   g_top[BH*NTOP];
__device__ float g_bcat[QS];
__device__ float g_sc[BH*NTOP*LL];
__device__ float g_mx[BH*NTOP];
__device__ float g_inv[BH*NTOP];
__device__ float g_part[4*BH*NTOP*DK];
__device__ uint16_t g_Cf16[ROWS*DD];      // x-f16 for QKV GEMM, later ctx for Wo
__device__ uint16_t g_H1f16[ROWS*DD];
__device__ uint16_t g_Gf16[ROWS*FFD];
__device__ uint16_t g_Wf16h[12*DD*DD];    // Wq@0,Wk@DW,Wv@2DW,Wo@3DW,W1@4DW,W2@8DW

__device__ __forceinline__ uint32_t smem_u32(const void* p){
    uint32_t a; asm("{ .reg .u64 t; cvta.to.shared.u64 t, %1; cvt.u32.u64 %0, t; }":"=r"(a):"l"(p)); return a;
}
__device__ __forceinline__ void cpasync16(uint32_t dst, const void* src){
    asm volatile("cp.async.cg.shared.global [%0], [%1], 16;" :: "r"(dst), "l"(src));
}
__device__ __forceinline__ void ldsm4(uint32_t* r, uint32_t addr){
    asm volatile("ldmatrix.sync.aligned.m8n8.x4.shared.b16 {%0,%1,%2,%3}, [%4];"
        : "=r"(r[0]),"=r"(r[1]),"=r"(r[2]),"=r"(r[3]) : "r"(addr));
}
__device__ __forceinline__ void mma_fp(float* c, const uint32_t* a, const uint32_t* b){
    asm volatile("mma.sync.aligned.m16n8k16.row.col.f32.f16.f16.f32 "
        "{%0,%1,%2,%3}, {%4,%5,%6,%7}, {%8,%9}, {%0,%1,%2,%3};"
        : "+f"(c[0]),"+f"(c[1]),"+f"(c[2]),"+f"(c[3])
        : "r"(a[0]),"r"(a[1]),"r"(a[2]),"r"(a[3]),"r"(b[0]),"r"(b[1]));
}
__device__ __forceinline__ uint32_t packh(__half a, __half b){
    return (uint32_t)__half_as_ushort(a) | ((uint32_t)__half_as_ushort(b)<<16);
}
__device__ __forceinline__ float2 h2f(uint32_t u){
    __half2 h = *reinterpret_cast<__half2*>(&u);
    return __half22float2(h);
}
// branchless exact-GELU (A&S 7.1.26 erf approx, max abs err 1.5e-7)
__device__ __forceinline__ float gelu_fast(float v){
    float av = fabsf(v);
    float t = __fdividef(1.0f, fmaf(0.70710678118654752440f*0.3275911f, av, 1.0f));
    float poly = t*(0.254829592f + t*(-0.284496736f + t*(1.421413741f + t*(-1.453152027f + t*1.061405429f))));
    float e = __expf(-0.5f*v*v);
    float erfv = copysignf(1.0f - poly*e, v);
    return 0.5f*v*(1.0f + erfv);
}

// =====================================================================
// HMMA GEMM: plain fp16 A x fp16 B, fp32 acc. BM=BN=128, BK=32, 256 thr,
// 2 CTAs/SM, 3-stage cp.async pipeline (stage = A|B = 20480B, x3 = 61440B).
// OUTMODE: 0 = fp32 C; 2 = fp16 C16; 3 = fp32 C + fp16 K-mirror (cols 512..1023).
// ACT=1: GELU.
// =====================================================================
template<int ACT, int OUTMODE>
__global__ void __launch_bounds__(256,2)
gemm_hmma(const uint16_t* __restrict__ A0, const uint16_t* __restrict__ B0,
          const float* __restrict__ bias, float* __restrict__ C,
          uint16_t* __restrict__ C16, int K, int ldc)
{
    extern __shared__ __align__(16) char sm[];
    const int t = threadIdx.x, lane = t&31, w = t>>5;
    const int wm = w>>2, wn = w&3;
    const int bm = blockIdx.y*128, bn = blockIdx.x*128;
    const int group = lane>>2, tig = lane&3;
    const uint32_t sbase = smem_u32(sm);
    const int STAGE = 20480;

    float acc[4][4][4];
    #pragma unroll
    for (int i=0;i<4;i++)
        #pragma unroll
        for (int j=0;j<4;j++)
            #pragma unroll
            for (int r=0;r<4;r++) acc[i][j][r]=0.f;

    const uint16_t* srcs[2] = {A0, B0};
    const int nch = K>>5;
    #pragma unroll
    for (int pc=0; pc<2; pc++){
        const int k0 = pc<<5;
        const uint32_t dst0 = sbase + pc*STAGE;
        #pragma unroll
        for (int u=0; u<4; u++){
            int q = t + u*256;
            int tile = q>>9, rem = q&511;
            int r = rem>>2, c = rem&3;
            const uint16_t* src = srcs[tile] + (size_t)(((tile<1)?bm:bn) + r)*K + k0 + c*8;
            cpasync16(dst0 + tile*10240 + r*80 + c*16, src);
        }
        asm volatile("cp.async.commit_group;");
    }
    const int brow_off = ((lane>>4)<<3) + (lane&7);
    const int bk_half  = (lane>>3)&1;
    int buf = 0;
    for (int ch=0; ch<nch; ch++){
        if (ch+2 < nch){
            const int k0 = (ch+2)<<5;
            int nb = buf+2; if (nb>=3) nb-=3;
            const uint32_t dst0 = sbase + nb*STAGE;
            #pragma unroll
            for (int u=0; u<4; u++){
                int q = t + u*256;
                int tile = q>>9, rem = q&511;
                int r = rem>>2, c = rem&3;
                const uint16_t* src = srcs[tile] + (size_t)(((tile<1)?bm:bn) + r)*K + k0 + c*8;
                cpasync16(dst0 + tile*10240 + r*80 + c*16, src);
            }
            asm volatile("cp.async.commit_group;");
            asm volatile("cp.async.wait_group 2;");
        } else if (ch+1 < nch){
            asm volatile("cp.async.wait_group 1;");
        } else {
            asm volatile("cp.async.wait_group 0;");
        }
        __syncthreads();
        const uint32_t stg = sbase + buf*STAGE;
        #pragma unroll
        for (int kk=0; kk<2; kk++){
            uint32_t a_h[4][4];
            #pragma unroll
            for (int mt=0; mt<4; mt++){
                uint32_t ra = stg + (uint32_t)((wm*64 + mt*16 + (lane&15))*80 + (lane>>4)*16 + kk*32);
                ldsm4(a_h[mt], ra);
            }
            #pragma unroll
            for (int ntp=0; ntp<2; ntp++){
                uint32_t bh4[4];
                uint32_t rb = stg + 10240u +
                    (uint32_t)((wn*32 + ntp*16 + brow_off)*80 + bk_half*16 + kk*32);
                ldsm4(bh4, rb);
                #pragma unroll
                for (int mt=0; mt<4; mt++){
                    mma_fp(acc[mt][2*ntp+0], a_h[mt], &bh4[0]);
                    mma_fp(acc[mt][2*ntp+1], a_h[mt], &bh4[2]);
                }
            }
        }
        __syncthreads();
        buf++; if (buf>=3) buf=0;
    }
    const bool kmirror = (OUTMODE==3) && (bn >= 512) && (bn < 1024);
    #pragma unroll
    for (int mt=0; mt<4; mt++){
        #pragma unroll
        for (int nt=0; nt<4; nt++){
            int r0  = bm + wm*64 + mt*16 + group;
            int col = bn + wn*32 + nt*8 + tig*2;
            float bb0 = bias[col], bb1 = bias[col+1];
            #pragma unroll
            for (int hh2=0; hh2<2; hh2++){
                int row = r0 + hh2*8;
                float v0 = acc[mt][nt][hh2*2+0] + bb0;
                float v1 = acc[mt][nt][hh2*2+1] + bb1;
                if (ACT==1){ v0 = gelu_fast(v0); v1 = gelu_fast(v1); }
                if (OUTMODE==2){
                    *(uint32_t*)(C16 + (size_t)row*ldc + col) =
                        packh(__float2half(v0), __float2half(v1));
                } else {
                    *(float2*)(C + (size_t)row*ldc + col) = make_float2(v0, v1);
                    if (kmirror){
                        *(uint32_t*)(C16 + (size_t)row*DD + (col-512)) =
                            packh(__float2half(v0), __float2half(v1));
                    }
                }
            }
        }
    }
}

// one fused conversion pass: Wq|Wk|Wv|Wo|W1|W2 -> fp16 weights, x -> fp16 A
__global__ void convert_all(const float* __restrict__ Wq, const float* __restrict__ Wk,
                            const float* __restrict__ Wv, const float* __restrict__ Wo,
                            const float* __restrict__ W1, const float* __restrict__ W2,
                            const float* __restrict__ x,
                            uint16_t* __restrict__ WFH, uint16_t* __restrict__ CF)
{
    int i = blockIdx.x*256 + threadIdx.x;       // float4 index over 1,835,008
    const float* src; uint16_t* dst; int rel;
    if      (i <  65536){ src=Wq; dst=WFH;        rel=i; }
    else if (i < 131072){ src=Wk; dst=WFH+1*DW;   rel=i-65536; }
    else if (i < 196608){ src=Wv; dst=WFH+2*DW;   rel=i-131072; }
    else if (i < 262144){ src=Wo; dst=WFH+3*DW;   rel=i-196608; }
    else if (i < 524288){ src=W1; dst=WFH+4*DW;   rel=i-262144; }
    else if (i < 786432){ src=W2; dst=WFH+8*DW;   rel=i-524288; }
    else                { src=x;  dst=CF;         rel=i-786432; }
    float4 v = ((const float4*)src)[rel];
    ((uint2*)dst)[rel] = make_uint2(packh(__float2half(v.x), __float2half(v.y)),
                                    packh(__float2half(v.z), __float2half(v.w)));
}

__global__ void bias_concat(const float* __restrict__ bq, const float* __restrict__ bk,
                            const float* __restrict__ bv)
{
    int t = blockIdx.x*256 + threadIdx.x;
    if (t>=QS) return;
    g_bcat[t] = (t<512)? bq[t] : (t<1024)? bk[t-512] : bv[t-1024];
}

// one warp per (bh,i): q fp32, K gathered from fp16 mirror (half the traffic)
__global__ void sample_scores_kernel(const int* __restrict__ idxs)
{
    int g = blockIdx.x*8 + (threadIdx.x>>5);
    int lane = threadIdx.x&31;
    int i = g&(LL-1), bh = g>>11, b = bh>>3, h = bh&7;
    const float2* qp = (const float2*)(g_QKV + (size_t)(b*LL+i)*QS + h*DK);
    float2 q = qp[lane];
    int myi0 = idxs[i*SK + lane];
    int myi1 = (lane<8)? idxs[i*SK + 32 + lane] : 0;
    const uint16_t* kbase = g_Kh + (size_t)b*LL*DD + h*DK;
    float mx = -INFINITY, sm = 0.f;
    #pragma unroll 4
    for (int j=0; j<SK; j++){
        int kidx = (j<32)? __shfl_sync(0xffffffffu, myi0, j)
                         : __shfl_sync(0xffffffffu, myi1, j-32);
        float2 kv = h2f(((const uint32_t*)(kbase + (size_t)kidx*DD))[lane]);
        float s = q.x*kv.x + q.y*kv.y;
        #pragma unroll
        for (int off=16; off; off>>=1) s += __shfl_xor_sync(0xffffffffu, s, off);
        mx = fmaxf(mx, s); sm += s;
    }
    if (lane==0) g_M[bh*LL+i] = mx - sm*(1.0f/LL);
}

__global__ void topk_kernel()
{
    int bh = blockIdx.x, t = threadIdx.x;
    __shared__ uint32_t su[LL];
    __shared__ int hist[256];
    __shared__ int s_bucket, s_taken;
    __shared__ int tsum[256];
    __shared__ int s_ctr;

    for (int l=t; l<LL; l+=256){
        uint32_t s = __float_as_uint(g_M[bh*LL+l]);
        su[l] = (s & 0x80000000u)? ~s : (s | 0x80000000u);
    }
    if (t==0) s_ctr = 0;
    __syncthreads();

    uint32_t prefix = 0;
    int remaining = NTOP;
    #pragma unroll
    for (int round=0; round<4; round++){
        int shift = 24 - round*8;
        hist[t] = 0;
        __syncthreads();
        for (int l=t; l<LL; l+=256){
            uint32_t u = su[l];
            bool m = (round==0) || (((u ^ prefix) >> (shift+8)) == 0u);
            if (m) atomicAdd(&hist[(u>>shift)&255], 1);
        }
        __syncthreads();
        if (t < 32){
            int loc[8], run = 0;
            #pragma unroll
            for (int k=0; k<8; k++){
                int b = 255 - (t*8 + k);
                loc[k] = run;
                run += hist[b];
            }
            int lane_total = run;
            int scan = lane_total;
            #pragma unroll
            for (int off=1; off<32; off<<=1){
                int v = __shfl_up_sync(0xffffffffu, scan, off);
                if (t >= off) scan += v;
            }
            int excl = scan - lane_total;
            #pragma unroll
            for (int k=0; k<8; k++){
                int b = 255 - (t*8 + k);
                int cumAbove = excl + loc[k];
                if (cumAbove < remaining && remaining <= cumAbove + hist[b]){
                    s_bucket = b;
                    s_taken  = cumAbove;
                }
            }
        }
        __syncthreads();
        prefix |= ((uint32_t)s_bucket) << shift;
        remaining -= s_taken;
        __syncthreads();
    }
    const uint32_t T = prefix;
    const int r = remaining;
    const int cnt_gt = NTOP - r;

    int base = t*8, c = 0;
    #pragma unroll
    for (int k=0; k<8; k++) if (su[base+k] == T) c++;
    tsum[t] = c;
    __syncthreads();
    for (int off=1; off<256; off<<=1){
        int v = (t>=off)? tsum[t-off] : 0;
        __syncthreads();
        tsum[t] += v;
        __syncthreads();
    }
    int excl = tsum[t] - c;
    #pragma unroll
    for (int k=0; k<8; k++){
        uint32_t u = su[base+k];
        if (u > T){
            int pos = atomicAdd(&s_ctr, 1);
            g_top[bh*NTOP + pos] = base + k;
        } else if (u == T){
            if (excl < r) g_top[bh*NTOP + cnt_gt + excl] = base + k;
            excl++;
        }
    }
}

__global__ void vmean_kernel()
{
    int bh = blockIdx.x, b = bh>>3, h = bh&7;
    int t = threadIdx.x, d = t&63, r0 = t>>6;
    float s = 0.f;
    for (int l=r0; l<LL; l+=4) s += g_QKV[(size_t)(b*LL+l)*QS + 1024 + h*DK + d];
    __shared__ float red[256];
    red[t]=s; __syncthreads();
    if (t<64) g_vmean[bh*DK+t] = (red[t]+red[t+64]+red[t+128]+red[t+192])*(1.0f/LL);
}

__global__ void ctx_bcast_kernel(uint16_t* __restrict__ c16)
{
    int i = blockIdx.x*256 + threadIdx.x;
    int row = i>>8, c2 = (i&255)*2;
    int b = row>>11, h = c2>>6;
    const float* vm = g_vmean + (b*HH+h)*DK;
    *(uint32_t*)(c16 + (size_t)row*DD + c2) =
        packh(__float2half(vm[c2&63]), __float2half(vm[(c2&63)+1]));
}

__global__ void attn_scores_kernel()
{
    int kt = blockIdx.x, bh = blockIdx.y, b = bh>>3, h = bh&7;
    int t = threadIdx.x;
    __shared__ float sq[NTOP][64];
    __shared__ __align__(16) float Ks[128][68];
    __shared__ int tops[NTOP];
    if (t < NTOP) tops[t] = g_top[bh*NTOP + t];
    __syncthreads();
    const size_t qkv = (size_t)b*LL*QS;
    for (int idx=t; idx<NTOP*64; idx+=128){
        int qn = idx>>6, d = idx&63;
        sq[qn][d] = g_QKV[qkv + (size_t)tops[qn]*QS + h*DK + d];
    }
    #pragma unroll
    for (int u=0; u<16; u++){
        int f = t + u*128;
        int r = f>>4, c = (f&15)<<2;
        float4 kv = *(const float4*)(&g_QKV[qkv + (size_t)(kt*128+r)*QS + 512 + h*DK + c]);
        *(float4*)(&Ks[r][c]) = kv;
    }
    __syncthreads();
    float acc[NTOP];
    #pragma unroll
    for (int qn=0; qn<NTOP; qn++) acc[qn]=0.f;
    for (int k2=0; k2<32; k2++){
        float2 kv = *(const float2*)(&Ks[t][k2*2]);
        #pragma unroll
        for (int qn=0; qn<NTOP; qn++){
            float2 qv = *(const float2*)(&sq[qn][k2*2]);
            acc[qn] += kv.x*qv.x + kv.y*qv.y;
        }
    }
    #pragma unroll
    for (int qn=0; qn<NTOP; qn++)
        g_sc[((size_t)bh*NTOP + qn)*LL + kt*128 + t] = acc[qn];
}

__global__ void attn_stats_kernel()
{
    int bh = blockIdx.x;
    int w = threadIdx.x>>5, lane = threadIdx.x&31;
    for (int j=0; j<5; j++){
        int qn = w*5 + j;
        const float* sp = g_sc + ((size_t)bh*NTOP + qn)*LL;
        float mx = -INFINITY;
        for (int i=lane; i<LL; i+=32) mx = fmaxf(mx, sp[i]);
        #pragma unroll
        for (int off=16; off; off>>=1) mx = fmaxf(mx, __shfl_xor_sync(0xffffffffu, mx, off));
        float sum = 0.f;
        for (int i=lane; i<LL; i+=32) sum += expf(sp[i]-mx);
        #pragma unroll
        for (int off=16; off; off>>=1) sum += __shfl_xor_sync(0xffffffffu, sum, off);
        if (lane==0){ g_mx[bh*NTOP+qn]=mx; g_inv[bh*NTOP+qn]=1.0f/sum; }
    }
}

__global__ void attn_pv_kernel()
{
    extern __shared__ __align__(16) float psm[];
    float* Vs  = psm;
    float* P   = psm + 8704;
    float* smx = psm + 8704 + 5160;
    int ks = blockIdx.x, bh = blockIdx.y, b = bh>>3, h = bh&7;
    int t = threadIdx.x;
    if (t < NTOP) smx[t] = g_mx[bh*NTOP + t];
    __syncthreads();
    const size_t qkv = (size_t)b*LL*QS;
    int qg = t>>5, d2 = (t&31)*2;
    float acc[5][2];
    #pragma unroll
    for (int j=0;j<5;j++){ acc[j][0]=0.f; acc[j][1]=0.f; }
    for (int kt=0; kt<4; kt++){
        int ktg = ks*4 + kt;
        #pragma unroll
        for (int u=0; u<8; u++){
            int f = t + u*256;
            int r = f>>4, c = (f&15)<<2;
            float4 vv = *(const float4*)(&g_QKV[qkv + (size_t)(ktg*128+r)*QS + 1024 + h*DK + c]);
            *(float4*)(&Vs[r*68 + c]) = vv;
        }
        #pragma unroll
        for (int u=0; u<20; u++){
            int idx = t + u*256;
            int qn = idx>>7, row = idx&127;
            float s = g_sc[((size_t)bh*NTOP + qn)*LL + ktg*128 + row];
            P[qn*129 + row] = expf(s - smx[qn]);
        }
        __syncthreads();
        for (int row=0; row<128; row++){
            float2 vv = *(const float2*)(&Vs[row*68 + d2]);
            #pragma unroll
            for (int j=0; j<5; j++){
                float p = P[(qg*5+j)*129 + row];
                acc[j][0] += p*vv.x;
                acc[j][1] += p*vv.y;
            }
        }
        __syncthreads();
    }
    #pragma unroll
    for (int j=0; j<5; j++){
        int qn = qg*5 + j;
        float* dst = g_part + ((size_t)(ks*BH + bh)*NTOP + qn)*DK + d2;
        dst[0] = acc[j][0];
        dst[1] = acc[j][1];
    }
}

__global__ void attn_combine_kernel(uint16_t* __restrict__ c16)
{
    int bh = blockIdx.x, b = bh>>3, h = bh&7;
    int t = threadIdx.x;
    __shared__ int tops[NTOP];
    __shared__ float sinv[NTOP];
    if (t < NTOP){ tops[t] = g_top[bh*NTOP+t]; sinv[t] = g_inv[bh*NTOP+t]; }
    __syncthreads();
    for (int e=t; e<NTOP*DK/2; e+=256){
        int qn = e>>5, d2 = (e&31)*2;
        float s0=0.f, s1=0.f;
        #pragma unroll
        for (int ks=0; ks<4; ks++){
            const float* pp = g_part + ((size_t)(ks*BH + bh)*NTOP + qn)*DK + d2;
            s0 += pp[0]; s1 += pp[1];
        }
        s0 *= sinv[qn]; s1 *= sinv[qn];
        size_t o = (size_t)(b*LL + tops[qn])*DD + h*DK + d2;
        *(uint32_t*)(c16 + o) = packh(__float2half(s0), __float2half(s1));
    }
}

template<int F16OUT>
__global__ void ln_add_kernel(const float* __restrict__ X, const float* __restrict__ Y,
                              const float* __restrict__ gg, const float* __restrict__ be,
                              float* __restrict__ out, uint16_t* __restrict__ o16)
{
    int row = blockIdx.x, t = threadIdx.x;
    float4 a = ((const float4*)(X + (size_t)row*DD))[t];
    float4 bq = ((const float4*)(Y + (size_t)row*DD))[t];
    float4 v = make_float4(a.x+bq.x, a.y+bq.y, a.z+bq.z, a.w+bq.w);
    float s = v.x+v.y+v.z+v.w;
    float ss = v.x*v.x+v.y*v.y+v.z*v.z+v.w*v.w;
    __shared__ float rs[128], rq[128];
    rs[t]=s; rq[t]=ss; __syncthreads();
    for (int k=64; k; k>>=1){ if (t<k){ rs[t]+=rs[t+k]; rq[t]+=rq[t+k]; } __syncthreads(); }
    float mean = rs[0]*(1.0f/DD);
    float var  = rq[0]*(1.0f/DD) - mean*mean;
    float rstd = rsqrtf(var + 1e-5f);
    float4 g4 = ((const float4*)gg)[t], b4 = ((const float4*)be)[t];
    float4 o;
    o.x=(v.x-mean)*rstd*g4.x+b4.x; o.y=(v.y-mean)*rstd*g4.y+b4.y;
    o.z=(v.z-mean)*rstd*g4.z+b4.z; o.w=(v.w-mean)*rstd*g4.w+b4.w;
    ((float4*)(out + (size_t)row*DD))[t] = o;
    if (F16OUT){
        ((uint2*)(o16 + (size_t)row*DD))[t] = make_uint2(
            packh(__float2half(o.x), __float2half(o.y)),
            packh(__float2half(o.z), __float2half(o.w)));
    }
}

extern "C" void kernel_launch(void* const* d_in, const int* in_sizes, int n_in,
                              void* d_out, int out_size)
{
    const float* x    = (const float*)d_in[0];
    const int*   idxs = (const int*)  d_in[1];
    const float* Wq = (const float*)d_in[2];  const float* bq = (const float*)d_in[3];
    const float* Wk = (const float*)d_in[4];  const float* bk = (const float*)d_in[5];
    const float* Wv = (const float*)d_in[6];  const float* bv = (const float*)d_in[7];
    const float* Wo = (const float*)d_in[8];  const float* bo = (const float*)d_in[9];
    const float* W1 = (const float*)d_in[10]; const float* b1 = (const float*)d_in[11];
    const float* W2 = (const float*)d_in[12]; const float* b2 = (const float*)d_in[13];
    const float* g1 = (const float*)d_in[14]; const float* be1 = (const float*)d_in[15];
    const float* g2 = (const float*)d_in[16]; const float* be2 = (const float*)d_in[17];
    float* out = (float*)d_out;

    float *QKV,*H1,*T0,*BCAT;
    uint16_t *KH,*CF,*H1F,*GF,*WFH;
    cudaGetSymbolAddress((void**)&QKV, g_QKV);
    cudaGetSymbolAddress((void**)&KH, g_Kh);
    cudaGetSymbolAddress((void**)&H1, g_h1);   cudaGetSymbolAddress((void**)&T0, g_t0);
    cudaGetSymbolAddress((void**)&BCAT, g_bcat);
    cudaGetSymbolAddress((void**)&CF, g_Cf16); cudaGetSymbolAddress((void**)&H1F, g_H1f16);
    cudaGetSymbolAddress((void**)&GF, g_Gf16);
    cudaGetSymbolAddress((void**)&WFH, g_Wf16h);

    const int SMEM = 61440;
    cudaFuncSetAttribute(gemm_hmma<0,0>, cudaFuncAttributeMaxDynamicSharedMemorySize, SMEM);
    cudaFuncSetAttribute(gemm_hmma<0,3>, cudaFuncAttributeMaxDynamicSharedMemorySize, SMEM);
    cudaFuncSetAttribute(gemm_hmma<1,2>, cudaFuncAttributeMaxDynamicSharedMemorySize, SMEM);
    cudaFuncSetAttribute(attn_pv_kernel, cudaFuncAttributeMaxDynamicSharedMemorySize, 55616);

    convert_all<<<7168, 256>>>(Wq, Wk, Wv, Wo, W1, W2, x, WFH, CF);
    bias_concat<<<QS/256, 256>>>(bq, bk, bv);

    dim3 gQKV(QS/128, ROWS/128), gD(DD/128, ROWS/128), gF(FFD/128, ROWS/128);
    gemm_hmma<0,3><<<gQKV, 256, SMEM>>>(CF, WFH, BCAT, QKV, KH, DD, QS);

    sample_scores_kernel<<<ROWS*HH/8, 256>>>(idxs);
    topk_kernel<<<BH, 256>>>();
    vmean_kernel<<<BH, 256>>>();
    ctx_bcast_kernel<<<ROWS*DD/512, 256>>>(CF);
    attn_scores_kernel<<<dim3(16, BH), 128>>>();
    attn_stats_kernel<<<BH, 256>>>();
    attn_pv_kernel<<<dim3(4, BH), 256, 55616>>>();
    attn_combine_kernel<<<BH, 256>>>(CF);

    gemm_hmma<0,0><<<gD, 256, SMEM>>>(CF, WFH+3*DW, bo, T0, 0, DD, DD);
    ln_add_kernel<1><<<ROWS, 128>>>(x, T0, g1, be1, H1, H1F);

    gemm_hmma<1,2><<<gF, 256, SMEM>>>(H1F, WFH+4*DW, b1, 0, GF, DD, FFD);
    gemm_hmma<0,0><<<gD, 256, SMEM>>>(GF, WFH+8*DW, b2, T0, 0, FFD, DD);
    ln_add_kernel<0><<<ROWS, 128>>>(H1, T0, g2, be2, out, 0);
}

// round 16
// speedup vs baseline: 1.3936x; 1.0421x over previous
#include <cuda_runtime.h>
#include <cuda_fp16.h>
#include <math.h>
#include <stdint.h>

#define BB 4
#define LL 2048
#define DD 512
#define HH 8
#define DK 64
#define FFD 2048
#define NTOP 40
#define SK 40
#define BH (BB*HH)
#define ROWS (BB*LL)
#define QS 1536
#define DW (DD*DD)

__device__ float g_QKV[ROWS*QS];
__device__ uint16_t g_Kh[ROWS*DD];        // fp16 mirror of K section (for sample gather)
__device__ float g_h1[ROWS*DD];
__device__ float g_t0[ROWS*DD];
__device__ float g_M[BH*LL];
__device__ float g_vmean[BH*DK];
__device__ int   g_top[BH*NTOP];
__device__ float g_bcat[QS];
__device__ float g_sc[BH*NTOP*LL];
__device__ float g_mx[BH*NTOP];
__device__ float g_inv[BH*NTOP];
__device__ float g_part[4*BH*NTOP*DK];
__device__ uint16_t g_Cf16[ROWS*DD];      // x-f16 for QKV GEMM, later ctx for Wo
__device__ uint16_t g_H1f16[ROWS*DD];
__device__ uint16_t g_Gf16[ROWS*FFD];
__device__ uint16_t g_Wf16h[12*DD*DD];    // Wq@0,Wk@DW,Wv@2DW,Wo@3DW,W1@4DW,W2@8DW

__device__ __forceinline__ uint32_t smem_u32(const void* p){
    uint32_t a; asm("{ .reg .u64 t; cvta.to.shared.u64 t, %1; cvt.u32.u64 %0, t; }":"=r"(a):"l"(p)); return a;
}
__device__ __forceinline__ void cpasync16(uint32_t dst, const void* src){
    asm volatile("cp.async.cg.shared.global [%0], [%1], 16;" :: "r"(dst), "l"(src));
}
__device__ __forceinline__ void ldsm4(uint32_t* r, uint32_t addr){
    asm volatile("ldmatrix.sync.aligned.m8n8.x4.shared.b16 {%0,%1,%2,%3}, [%4];"
        : "=r"(r[0]),"=r"(r[1]),"=r"(r[2]),"=r"(r[3]) : "r"(addr));
}
__device__ __forceinline__ void mma_fp(float* c, const uint32_t* a, const uint32_t* b){
    asm volatile("mma.sync.aligned.m16n8k16.row.col.f32.f16.f16.f32 "
        "{%0,%1,%2,%3}, {%4,%5,%6,%7}, {%8,%9}, {%0,%1,%2,%3};"
        : "+f"(c[0]),"+f"(c[1]),"+f"(c[2]),"+f"(c[3])
        : "r"(a[0]),"r"(a[1]),"r"(a[2]),"r"(a[3]),"r"(b[0]),"r"(b[1]));
}
__device__ __forceinline__ uint32_t packh(__half a, __half b){
    return (uint32_t)__half_as_ushort(a) | ((uint32_t)__half_as_ushort(b)<<16);
}
__device__ __forceinline__ float2 h2f(uint32_t u){
    __half2 h = *reinterpret_cast<__half2*>(&u);
    return __half22float2(h);
}
// branchless exact-GELU (A&S 7.1.26 erf approx, max abs err 1.5e-7)
__device__ __forceinline__ float gelu_fast(float v){
    float av = fabsf(v);
    float t = __fdividef(1.0f, fmaf(0.70710678118654752440f*0.3275911f, av, 1.0f));
    float poly = t*(0.254829592f + t*(-0.284496736f + t*(1.421413741f + t*(-1.453152027f + t*1.061405429f))));
    float e = __expf(-0.5f*v*v);
    float erfv = copysignf(1.0f - poly*e, v);
    return 0.5f*v*(1.0f + erfv);
}

// =====================================================================
// HMMA GEMM: plain fp16 A x fp16 B, fp32 acc. BM=BN=128, BK=32, 256 thr,
// 2 CTAs/SM, 3-stage cp.async pipeline (stage = A|B = 20480B, x3 = 61440B).
// OUTMODE: 0 = fp32 C; 2 = fp16 C16; 3 = fp32 C + fp16 K-mirror (cols 512..1023).
// ACT=1: GELU.
// =====================================================================
template<int ACT, int OUTMODE>
__global__ void __launch_bounds__(256,2)
gemm_hmma(const uint16_t* __restrict__ A0, const uint16_t* __restrict__ B0,
          const float* __restrict__ bias, float* __restrict__ C,
          uint16_t* __restrict__ C16, int K, int ldc)
{
    extern __shared__ __align__(16) char sm[];
    const int t = threadIdx.x, lane = t&31, w = t>>5;
    const int wm = w>>2, wn = w&3;
    const int bm = blockIdx.y*128, bn = blockIdx.x*128;
    const int group = lane>>2, tig = lane&3;
    const uint32_t sbase = smem_u32(sm);
    const int STAGE = 20480;

    float acc[4][4][4];
    #pragma unroll
    for (int i=0;i<4;i++)
        #pragma unroll
        for (int j=0;j<4;j++)
            #pragma unroll
            for (int r=0;r<4;r++) acc[i][j][r]=0.f;

    const uint16_t* srcs[2] = {A0, B0};
    const int nch = K>>5;
    #pragma unroll
    for (int pc=0; pc<2; pc++){
        const int k0 = pc<<5;
        const uint32_t dst0 = sbase + pc*STAGE;
        #pragma unroll
        for (int u=0; u<4; u++){
            int q = t + u*256;
            int tile = q>>9, rem = q&511;
            int r = rem>>2, c = rem&3;
            const uint16_t* src = srcs[tile] + (size_t)(((tile<1)?bm:bn) + r)*K + k0 + c*8;
            cpasync16(dst0 + tile*10240 + r*80 + c*16, src);
        }
        asm volatile("cp.async.commit_group;");
    }
    const int brow_off = ((lane>>4)<<3) + (lane&7);
    const int bk_half  = (lane>>3)&1;
    int buf = 0;
    for (int ch=0; ch<nch; ch++){
        if (ch+2 < nch){
            const int k0 = (ch+2)<<5;
            int nb = buf+2; if (nb>=3) nb-=3;
            const uint32_t dst0 = sbase + nb*STAGE;
            #pragma unroll
            for (int u=0; u<4; u++){
                int q = t + u*256;
                int tile = q>>9, rem = q&511;
                int r = rem>>2, c = rem&3;
                const uint16_t* src = srcs[tile] + (size_t)(((tile<1)?bm:bn) + r)*K + k0 + c*8;
                cpasync16(dst0 + tile*10240 + r*80 + c*16, src);
            }
            asm volatile("cp.async.commit_group;");
            asm volatile("cp.async.wait_group 2;");
        } else if (ch+1 < nch){
            asm volatile("cp.async.wait_group 1;");
        } else {
            asm volatile("cp.async.wait_group 0;");
        }
        __syncthreads();
        const uint32_t stg = sbase + buf*STAGE;
        #pragma unroll
        for (int kk=0; kk<2; kk++){
            uint32_t a_h[4][4];
            #pragma unroll
            for (int mt=0; mt<4; mt++){
                uint32_t ra = stg + (uint32_t)((wm*64 + mt*16 + (lane&15))*80 + (lane>>4)*16 + kk*32);
                ldsm4(a_h[mt], ra);
            }
            #pragma unroll
            for (int ntp=0; ntp<2; ntp++){
                uint32_t bh4[4];
                uint32_t rb = stg + 10240u +
                    (uint32_t)((wn*32 + ntp*16 + brow_off)*80 + bk_half*16 + kk*32);
                ldsm4(bh4, rb);
                #pragma unroll
                for (int mt=0; mt<4; mt++){
                    mma_fp(acc[mt][2*ntp+0], a_h[mt], &bh4[0]);
                    mma_fp(acc[mt][2*ntp+1], a_h[mt], &bh4[2]);
                }
            }
        }
        __syncthreads();
        buf++; if (buf>=3) buf=0;
    }
    const bool kmirror = (OUTMODE==3) && (bn >= 512) && (bn < 1024);
    #pragma unroll
    for (int mt=0; mt<4; mt++){
        #pragma unroll
        for (int nt=0; nt<4; nt++){
            int r0  = bm + wm*64 + mt*16 + group;
            int col = bn + wn*32 + nt*8 + tig*2;
            float bb0 = bias[col], bb1 = bias[col+1];
            #pragma unroll
            for (int hh2=0; hh2<2; hh2++){
                int row = r0 + hh2*8;
                float v0 = acc[mt][nt][hh2*2+0] + bb0;
                float v1 = acc[mt][nt][hh2*2+1] + bb1;
                if (ACT==1){ v0 = gelu_fast(v0); v1 = gelu_fast(v1); }
                if (OUTMODE==2){
                    *(uint32_t*)(C16 + (size_t)row*ldc + col) =
                        packh(__float2half(v0), __float2half(v1));
                } else {
                    *(float2*)(C + (size_t)row*ldc + col) = make_float2(v0, v1);
                    if (kmirror){
                        *(uint32_t*)(C16 + (size_t)row*DD + (col-512)) =
                            packh(__float2half(v0), __float2half(v1));
                    }
                }
            }
        }
    }
}

// one fused conversion pass: Wq|Wk|Wv|Wo|W1|W2 -> fp16 weights, x -> fp16 A
__global__ void convert_all(const float* __restrict__ Wq, const float* __restrict__ Wk,
                            const float* __restrict__ Wv, const float* __restrict__ Wo,
                            const float* __restrict__ W1, const float* __restrict__ W2,
                            const float* __restrict__ x,
                            uint16_t* __restrict__ WFH, uint16_t* __restrict__ CF)
{
    int i = blockIdx.x*256 + threadIdx.x;       // float4 index over 1,835,008
    const float* src; uint16_t* dst; int rel;
    if      (i <  65536){ src=Wq; dst=WFH;        rel=i; }
    else if (i < 131072){ src=Wk; dst=WFH+1*DW;   rel=i-65536; }
    else if (i < 196608){ src=Wv; dst=WFH+2*DW;   rel=i-131072; }
    else if (i < 262144){ src=Wo; dst=WFH+3*DW;   rel=i-196608; }
    else if (i < 524288){ src=W1; dst=WFH+4*DW;   rel=i-262144; }
    else if (i < 786432){ src=W2; dst=WFH+8*DW;   rel=i-524288; }
    else                { src=x;  dst=CF;         rel=i-786432; }
    float4 v = ((const float4*)src)[rel];
    ((uint2*)dst)[rel] = make_uint2(packh(__float2half(v.x), __float2half(v.y)),
                                    packh(__float2half(v.z), __float2half(v.w)));
}

__global__ void bias_concat(const float* __restrict__ bq, const float* __restrict__ bk,
                            const float* __restrict__ bv)
{
    int t = blockIdx.x*256 + threadIdx.x;
    if (t>=QS) return;
    g_bcat[t] = (t<512)? bq[t] : (t<1024)? bk[t-512] : bv[t-1024];
}

// one warp per (bh,i): batched gathers (8 in flight) to hide L2 latency
__global__ void sample_scores_kernel(const int* __restrict__ idxs)
{
    int g = blockIdx.x*8 + (threadIdx.x>>5);
    int lane = threadIdx.x&31;
    int i = g&(LL-1), bh = g>>11, b = bh>>3, h = bh&7;
    const float2* qp = (const float2*)(g_QKV + (size_t)(b*LL+i)*QS + h*DK);
    float2 q = qp[lane];
    int myi0 = idxs[i*SK + lane];
    int myi1 = (lane<8)? idxs[i*SK + 32 + lane] : 0;
    const uint16_t* kbase = g_Kh + (size_t)b*LL*DD + h*DK;
    float mx = -INFINITY, sm = 0.f;
    #pragma unroll
    for (int jb=0; jb<SK; jb+=8){
        uint32_t kw[8];
        #pragma unroll
        for (int u=0; u<8; u++){
            int j = jb + u;
            int kidx = (j<32)? __shfl_sync(0xffffffffu, myi0, j)
                             : __shfl_sync(0xffffffffu, myi1, j-32);
            kw[u] = ((const uint32_t*)(kbase + (size_t)kidx*DD))[lane];
        }
        #pragma unroll
        for (int u=0; u<8; u++){
            float2 kv = h2f(kw[u]);
            float s = q.x*kv.x + q.y*kv.y;
            #pragma unroll
            for (int off=16; off; off>>=1) s += __shfl_xor_sync(0xffffffffu, s, off);
            mx = fmaxf(mx, s); sm += s;
        }
    }
    if (lane==0) g_M[bh*LL+i] = mx - sm*(1.0f/LL);
}

__global__ void topk_kernel()
{
    int bh = blockIdx.x, t = threadIdx.x;
    __shared__ uint32_t su[LL];
    __shared__ int hist[256];
    __shared__ int s_bucket, s_taken;
    __shared__ int tsum[256];
    __shared__ int s_ctr;

    for (int l=t; l<LL; l+=256){
        uint32_t s = __float_as_uint(g_M[bh*LL+l]);
        su[l] = (s & 0x80000000u)? ~s : (s | 0x80000000u);
    }
    if (t==0) s_ctr = 0;
    __syncthreads();

    uint32_t prefix = 0;
    int remaining = NTOP;
    #pragma unroll
    for (int round=0; round<4; round++){
        int shift = 24 - round*8;
        hist[t] = 0;
        __syncthreads();
        for (int l=t; l<LL; l+=256){
            uint32_t u = su[l];
            bool m = (round==0) || (((u ^ prefix) >> (shift+8)) == 0u);
            if (m) atomicAdd(&hist[(u>>shift)&255], 1);
        }
        __syncthreads();
        if (t < 32){
            int loc[8], run = 0;
            #pragma unroll
            for (int k=0; k<8; k++){
                int b = 255 - (t*8 + k);
                loc[k] = run;
                run += hist[b];
            }
            int lane_total = run;
            int scan = lane_total;
            #pragma unroll
            for (int off=1; off<32; off<<=1){
                int v = __shfl_up_sync(0xffffffffu, scan, off);
                if (t >= off) scan += v;
            }
            int excl = scan - lane_total;
            #pragma unroll
            for (int k=0; k<8; k++){
                int b = 255 - (t*8 + k);
                int cumAbove = excl + loc[k];
                if (cumAbove < remaining && remaining <= cumAbove + hist[b]){
                    s_bucket = b;
                    s_taken  = cumAbove;
                }
            }
        }
        __syncthreads();
        prefix |= ((uint32_t)s_bucket) << shift;
        remaining -= s_taken;
        __syncthreads();
    }
    const uint32_t T = prefix;
    const int r = remaining;
    const int cnt_gt = NTOP - r;

    int base = t*8, c = 0;
    #pragma unroll
    for (int k=0; k<8; k++) if (su[base+k] == T) c++;
    tsum[t] = c;
    __syncthreads();
    for (int off=1; off<256; off<<=1){
        int v = (t>=off)? tsum[t-off] : 0;
        __syncthreads();
        tsum[t] += v;
        __syncthreads();
    }
    int excl = tsum[t] - c;
    #pragma unroll
    for (int k=0; k<8; k++){
        uint32_t u = su[base+k];
        if (u > T){
            int pos = atomicAdd(&s_ctr, 1);
            g_top[bh*NTOP + pos] = base + k;
        } else if (u == T){
            if (excl < r) g_top[bh*NTOP + cnt_gt + excl] = base + k;
            excl++;
        }
    }
}

__global__ void vmean_kernel()
{
    int bh = blockIdx.x, b = bh>>3, h = bh&7;
    int t = threadIdx.x, d = t&63, r0 = t>>6;
    float s = 0.f;
    for (int l=r0; l<LL; l+=4) s += g_QKV[(size_t)(b*LL+l)*QS + 1024 + h*DK + d];
    __shared__ float red[256];
    red[t]=s; __syncthreads();
    if (t<64) g_vmean[bh*DK+t] = (red[t]+red[t+64]+red[t+128]+red[t+192])*(1.0f/LL);
}

__global__ void ctx_bcast_kernel(uint16_t* __restrict__ c16)
{
    int i = blockIdx.x*256 + threadIdx.x;
    int row = i>>8, c2 = (i&255)*2;
    int b = row>>11, h = c2>>6;
    const float* vm = g_vmean + (b*HH+h)*DK;
    *(uint32_t*)(c16 + (size_t)row*DD + c2) =
        packh(__float2half(vm[c2&63]), __float2half(vm[(c2&63)+1]));
}

__global__ void attn_scores_kernel()
{
    int kt = blockIdx.x, bh = blockIdx.y, b = bh>>3, h = bh&7;
    int t = threadIdx.x;
    __shared__ float sq[NTOP][64];
    __shared__ __align__(16) float Ks[128][68];
    __shared__ int tops[NTOP];
    if (t < NTOP) tops[t] = g_top[bh*NTOP + t];
    __syncthreads();
    const size_t qkv = (size_t)b*LL*QS;
    for (int idx=t; idx<NTOP*64; idx+=128){
        int qn = idx>>6, d = idx&63;
        sq[qn][d] = g_QKV[qkv + (size_t)tops[qn]*QS + h*DK + d];
    }
    #pragma unroll
    for (int u=0; u<16; u++){
        int f = t + u*128;
        int r = f>>4, c = (f&15)<<2;
        float4 kv = *(const float4*)(&g_QKV[qkv + (size_t)(kt*128+r)*QS + 512 + h*DK + c]);
        *(float4*)(&Ks[r][c]) = kv;
    }
    __syncthreads();
    float acc[NTOP];
    #pragma unroll
    for (int qn=0; qn<NTOP; qn++) acc[qn]=0.f;
    for (int k2=0; k2<32; k2++){
        float2 kv = *(const float2*)(&Ks[t][k2*2]);
        #pragma unroll
        for (int qn=0; qn<NTOP; qn++){
            float2 qv = *(const float2*)(&sq[qn][k2*2]);
            acc[qn] += kv.x*qv.x + kv.y*qv.y;
        }
    }
    #pragma unroll
    for (int qn=0; qn<NTOP; qn++)
        g_sc[((size_t)bh*NTOP + qn)*LL + kt*128 + t] = acc[qn];
}

__global__ void attn_stats_kernel()
{
    int bh = blockIdx.x;
    int w = threadIdx.x>>5, lane = threadIdx.x&31;
    for (int j=0; j<5; j++){
        int qn = w*5 + j;
        const float* sp = g_sc + ((size_t)bh*NTOP + qn)*LL;
        float mx = -INFINITY;
        for (int i=lane; i<LL; i+=32) mx = fmaxf(mx, sp[i]);
        #pragma unroll
        for (int off=16; off; off>>=1) mx = fmaxf(mx, __shfl_xor_sync(0xffffffffu, mx, off));
        float sum = 0.f;
        for (int i=lane; i<LL; i+=32) sum += expf(sp[i]-mx);
        #pragma unroll
        for (int off=16; off; off>>=1) sum += __shfl_xor_sync(0xffffffffu, sum, off);
        if (lane==0){ g_mx[bh*NTOP+qn]=mx; g_inv[bh*NTOP+qn]=1.0f/sum; }
    }
}

__global__ void attn_pv_kernel()
{
    extern __shared__ __align__(16) float psm[];
    float* Vs  = psm;
    float* P   = psm + 8704;
    float* smx = psm + 8704 + 5160;
    int ks = blockIdx.x, bh = blockIdx.y, b = bh>>3, h = bh&7;
    int t = threadIdx.x;
    if (t < NTOP) smx[t] = g_mx[bh*NTOP + t];
    __syncthreads();
    const size_t qkv = (size_t)b*LL*QS;
    int qg = t>>5, d2 = (t&31)*2;
    float acc[5][2];
    #pragma unroll
    for (int j=0;j<5;j++){ acc[j][0]=0.f; acc[j][1]=0.f; }
    for (int kt=0; kt<4; kt++){
        int ktg = ks*4 + kt;
        #pragma unroll
        for (int u=0; u<8; u++){
            int f = t + u*256;
            int r = f>>4, c = (f&15)<<2;
            float4 vv = *(const float4*)(&g_QKV[qkv + (size_t)(ktg*128+r)*QS + 1024 + h*DK + c]);
            *(float4*)(&Vs[r*68 + c]) = vv;
        }
        #pragma unroll
        for (int u=0; u<20; u++){
            int idx = t + u*256;
            int qn = idx>>7, row = idx&127;
            float s = g_sc[((size_t)bh*NTOP + qn)*LL + ktg*128 + row];
            P[qn*129 + row] = expf(s - smx[qn]);
        }
        __syncthreads();
        for (int row=0; row<128; row++){
            float2 vv = *(const float2*)(&Vs[row*68 + d2]);
            #pragma unroll
            for (int j=0; j<5; j++){
                float p = P[(qg*5+j)*129 + row];
                acc[j][0] += p*vv.x;
                acc[j][1] += p*vv.y;
            }
        }
        __syncthreads();
    }
    #pragma unroll
    for (int j=0; j<5; j++){
        int qn = qg*5 + j;
        float* dst = g_part + ((size_t)(ks*BH + bh)*NTOP + qn)*DK + d2;
        dst[0] = acc[j][0];
        dst[1] = acc[j][1];
    }
}

__global__ void attn_combine_kernel(uint16_t* __restrict__ c16)
{
    int bh = blockIdx.x, b = bh>>3, h = bh&7;
    int t = threadIdx.x;
    __shared__ int tops[NTOP];
    __shared__ float sinv[NTOP];
    if (t < NTOP){ tops[t] = g_top[bh*NTOP+t]; sinv[t] = g_inv[bh*NTOP+t]; }
    __syncthreads();
    for (int e=t; e<NTOP*DK/2; e+=256){
        int qn = e>>5, d2 = (e&31)*2;
        float s0=0.f, s1=0.f;
        #pragma unroll
        for (int ks=0; ks<4; ks++){
            const float* pp = g_part + ((size_t)(ks*BH + bh)*NTOP + qn)*DK + d2;
            s0 += pp[0]; s1 += pp[1];
        }
        s0 *= sinv[qn]; s1 *= sinv[qn];
        size_t o = (size_t)(b*LL + tops[qn])*DD + h*DK + d2;
        *(uint32_t*)(c16 + o) = packh(__float2half(s0), __float2half(s1));
    }
}

template<int F16OUT>
__global__ void ln_add_kernel(const float* __restrict__ X, const float* __restrict__ Y,
                              const float* __restrict__ gg, const float* __restrict__ be,
                              float* __restrict__ out, uint16_t* __restrict__ o16)
{
    int row = blockIdx.x, t = threadIdx.x;
    float4 a = ((const float4*)(X + (size_t)row*DD))[t];
    float4 bq = ((const float4*)(Y + (size_t)row*DD))[t];
    float4 v = make_float4(a.x+bq.x, a.y+bq.y, a.z+bq.z, a.w+bq.w);
    float s = v.x+v.y+v.z+v.w;
    float ss = v.x*v.x+v.y*v.y+v.z*v.z+v.w*v.w;
    __shared__ float rs[128], rq[128];
    rs[t]=s; rq[t]=ss; __syncthreads();
    for (int k=64; k; k>>=1){ if (t<k){ rs[t]+=rs[t+k]; rq[t]+=rq[t+k]; } __syncthreads(); }
    float mean = rs[0]*(1.0f/DD);
    float var  = rq[0]*(1.0f/DD) - mean*mean;
    float rstd = rsqrtf(var + 1e-5f);
    float4 g4 = ((const float4*)gg)[t], b4 = ((const float4*)be)[t];
    float4 o;
    o.x=(v.x-mean)*rstd*g4.x+b4.x; o.y=(v.y-mean)*rstd*g4.y+b4.y;
    o.z=(v.z-mean)*rstd*g4.z+b4.z; o.w=(v.w-mean)*rstd*g4.w+b4.w;
    ((float4*)(out + (size_t)row*DD))[t] = o;
    if (F16OUT){
        ((uint2*)(o16 + (size_t)row*DD))[t] = make_uint2(
            packh(__float2half(o.x), __float2half(o.y)),
            packh(__float2half(o.z), __float2half(o.w)));
    }
}

extern "C" void kernel_launch(void* const* d_in, const int* in_sizes, int n_in,
                              void* d_out, int out_size)
{
    const float* x    = (const float*)d_in[0];
    const int*   idxs = (const int*)  d_in[1];
    const float* Wq = (const float*)d_in[2];  const float* bq = (const float*)d_in[3];
    const float* Wk = (const float*)d_in[4];  const float* bk = (const float*)d_in[5];
    const float* Wv = (const float*)d_in[6];  const float* bv = (const float*)d_in[7];
    const float* Wo = (const float*)d_in[8];  const float* bo = (const float*)d_in[9];
    const float* W1 = (const float*)d_in[10]; const float* b1 = (const float*)d_in[11];
    const float* W2 = (const float*)d_in[12]; const float* b2 = (const float*)d_in[13];
    const float* g1 = (const float*)d_in[14]; const float* be1 = (const float*)d_in[15];
    const float* g2 = (const float*)d_in[16]; const float* be2 = (const float*)d_in[17];
    float* out = (float*)d_out;

    float *QKV,*H1,*T0,*BCAT;
    uint16_t *KH,*CF,*H1F,*GF,*WFH;
    cudaGetSymbolAddress((void**)&QKV, g_QKV);
    cudaGetSymbolAddress((void**)&KH, g_Kh);
    cudaGetSymbolAddress((void**)&H1, g_h1);   cudaGetSymbolAddress((void**)&T0, g_t0);
    cudaGetSymbolAddress((void**)&BCAT, g_bcat);
    cudaGetSymbolAddress((void**)&CF, g_Cf16); cudaGetSymbolAddress((void**)&H1F, g_H1f16);
    cudaGetSymbolAddress((void**)&GF, g_Gf16);
    cudaGetSymbolAddress((void**)&WFH, g_Wf16h);

    const int SMEM = 61440;
    cudaFuncSetAttribute(gemm_hmma<0,0>, cudaFuncAttributeMaxDynamicSharedMemorySize, SMEM);
    cudaFuncSetAttribute(gemm_hmma<0,3>, cudaFuncAttributeMaxDynamicSharedMemorySize, SMEM);
    cudaFuncSetAttribute(gemm_hmma<1,2>, cudaFuncAttributeMaxDynamicSharedMemorySize, SMEM);
    cudaFuncSetAttribute(attn_pv_kernel, cudaFuncAttributeMaxDynamicSharedMemorySize, 55616);

    convert_all<<<7168, 256>>>(Wq, Wk, Wv, Wo, W1, W2, x, WFH, CF);
    bias_concat<<<QS/256, 256>>>(bq, bk, bv);

    dim3 gQKV(QS/128, ROWS/128), gD(DD/128, ROWS/128), gF(FFD/128, ROWS/128);
    gemm_hmma<0,3><<<gQKV, 256, SMEM>>>(CF, WFH, BCAT, QKV, KH, DD, QS);

    sample_scores_kernel<<<ROWS*HH/8, 256>>>(idxs);
    topk_kernel<<<BH, 256>>>();
    vmean_kernel<<<BH, 256>>>();
    ctx_bcast_kernel<<<ROWS*DD/512, 256>>>(CF);
    attn_scores_kernel<<<dim3(16, BH), 128>>>();
    attn_stats_kernel<<<BH, 256>>>();
    attn_pv_kernel<<<dim3(4, BH), 256, 55616>>>();
    attn_combine_kernel<<<BH, 256>>>(CF);

    gemm_hmma<0,0><<<gD, 256, SMEM>>>(CF, WFH+3*DW, bo, T0, 0, DD, DD);
    ln_add_kernel<1><<<ROWS, 128>>>(x, T0, g1, be1, H1, H1F);

    gemm_hmma<1,2><<<gF, 256, SMEM>>>(H1F, WFH+4*DW, b1, 0, GF, DD, FFD);
    gemm_hmma<0,0><<<gD, 256, SMEM>>>(GF, WFH+8*DW, b2, T0, 0, FFD, DD);
    ln_add_kernel<0><<<ROWS, 128>>>(H1, T0, g2, be2, out, 0);
}

// round 17
// speedup vs baseline: 1.5269x; 1.0957x over previous
#include <cuda_runtime.h>
#include <cuda_fp16.h>
#include <math.h>
#include <stdint.h>

#define BB 4
#define LL 2048
#define DD 512
#define HH 8
#define DK 64
#define FFD 2048
#define NTOP 40
#define SK 40
#define BH (BB*HH)
#define ROWS (BB*LL)
#define QS 1536
#define DW (DD*DD)

__device__ float g_QKV[ROWS*QS];
__device__ uint16_t g_Kh[ROWS*DD];        // fp16 mirror of K section (for sample gather)
__device__ float g_h1[ROWS*DD];
__device__ float g_t0[ROWS*DD];
__device__ float g_M[BH*LL];
__device__ float g_vmean[BH*DK];
__device__ int   g_top[BH*NTOP];
__device__ float g_bcat[QS];
__device__ float g_sc[BH*NTOP*LL];
__device__ float g_mx[BH*NTOP];
__device__ float g_inv[BH*NTOP];
__device__ float g_part[4*BH*NTOP*DK];
__device__ uint16_t g_Cf16[ROWS*DD];
__device__ uint16_t g_H1f16[ROWS*DD];
__device__ uint16_t g_Gf16[ROWS*FFD];
__device__ uint16_t g_Wf16h[12*DD*DD];    // Wq@0,Wk@DW,Wv@2DW,Wo@3DW,W1@4DW,W2@8DW

__device__ __forceinline__ uint32_t smem_u32(const void* p){
    uint32_t a; asm("{ .reg .u64 t; cvta.to.shared.u64 t, %1; cvt.u32.u64 %0, t; }":"=r"(a):"l"(p)); return a;
}
__device__ __forceinline__ void cpasync16(uint32_t dst, const void* src){
    asm volatile("cp.async.cg.shared.global [%0], [%1], 16;" :: "r"(dst), "l"(src));
}
__device__ __forceinline__ void ldsm4(uint32_t* r, uint32_t addr){
    asm volatile("ldmatrix.sync.aligned.m8n8.x4.shared.b16 {%0,%1,%2,%3}, [%4];"
        : "=r"(r[0]),"=r"(r[1]),"=r"(r[2]),"=r"(r[3]) : "r"(addr));
}
__device__ __forceinline__ void mma_fp(float* c, const uint32_t* a, const uint32_t* b){
    asm volatile("mma.sync.aligned.m16n8k16.row.col.f32.f16.f16.f32 "
        "{%0,%1,%2,%3}, {%4,%5,%6,%7}, {%8,%9}, {%0,%1,%2,%3};"
        : "+f"(c[0]),"+f"(c[1]),"+f"(c[2]),"+f"(c[3])
        : "r"(a[0]),"r"(a[1]),"r"(a[2]),"r"(a[3]),"r"(b[0]),"r"(b[1]));
}
__device__ __forceinline__ uint32_t packh(__half a, __half b){
    return (uint32_t)__half_as_ushort(a) | ((uint32_t)__half_as_ushort(b)<<16);
}
__device__ __forceinline__ float2 h2f(uint32_t u){
    __half2 h = *reinterpret_cast<__half2*>(&u);
    return __half22float2(h);
}
// branchless exact-GELU (A&S 7.1.26 erf approx, max abs err 1.5e-7)
__device__ __forceinline__ float gelu_fast(float v){
    float av = fabsf(v);
    float t = __fdividef(1.0f, fmaf(0.70710678118654752440f*0.3275911f, av, 1.0f));
    float poly = t*(0.254829592f + t*(-0.284496736f + t*(1.421413741f + t*(-1.453152027f + t*1.061405429f))));
    float e = __expf(-0.5f*v*v);
    float erfv = copysignf(1.0f - poly*e, v);
    return 0.5f*v*(1.0f + erfv);
}

// =====================================================================
// HMMA GEMM: plain fp16 A x fp16 B, fp32 acc. BM=BN=128, BK=32, 256 thr,
// 2 CTAs/SM, 3-stage cp.async pipeline (stage = A|B = 20480B, x3 = 61440B).
// OUTMODE: 0 = fp32 C; 2 = fp16 C16; 3 = fp32 C + fp16 K-mirror (cols 512..1023).
// ACT=1: GELU.
// =====================================================================
template<int ACT, int OUTMODE>
__global__ void __launch_bounds__(256,2)
gemm_hmma(const uint16_t* __restrict__ A0, const uint16_t* __restrict__ B0,
          const float* __restrict__ bias, float* __restrict__ C,
          uint16_t* __restrict__ C16, int K, int ldc)
{
    extern __shared__ __align__(16) char sm[];
    const int t = threadIdx.x, lane = t&31, w = t>>5;
    const int wm = w>>2, wn = w&3;
    const int bm = blockIdx.y*128, bn = blockIdx.x*128;
    const int group = lane>>2, tig = lane&3;
    const uint32_t sbase = smem_u32(sm);
    const int STAGE = 20480;

    float acc[4][4][4];
    #pragma unroll
    for (int i=0;i<4;i++)
        #pragma unroll
        for (int j=0;j<4;j++)
            #pragma unroll
            for (int r=0;r<4;r++) acc[i][j][r]=0.f;

    const uint16_t* srcs[2] = {A0, B0};
    const int nch = K>>5;
    #pragma unroll
    for (int pc=0; pc<2; pc++){
        const int k0 = pc<<5;
        const uint32_t dst0 = sbase + pc*STAGE;
        #pragma unroll
        for (int u=0; u<4; u++){
            int q = t + u*256;
            int tile = q>>9, rem = q&511;
            int r = rem>>2, c = rem&3;
            const uint16_t* src = srcs[tile] + (size_t)(((tile<1)?bm:bn) + r)*K + k0 + c*8;
            cpasync16(dst0 + tile*10240 + r*80 + c*16, src);
        }
        asm volatile("cp.async.commit_group;");
    }
    const int brow_off = ((lane>>4)<<3) + (lane&7);
    const int bk_half  = (lane>>3)&1;
    int buf = 0;
    for (int ch=0; ch<nch; ch++){
        if (ch+2 < nch){
            const int k0 = (ch+2)<<5;
            int nb = buf+2; if (nb>=3) nb-=3;
            const uint32_t dst0 = sbase + nb*STAGE;
            #pragma unroll
            for (int u=0; u<4; u++){
                int q = t + u*256;
                int tile = q>>9, rem = q&511;
                int r = rem>>2, c = rem&3;
                const uint16_t* src = srcs[tile] + (size_t)(((tile<1)?bm:bn) + r)*K + k0 + c*8;
                cpasync16(dst0 + tile*10240 + r*80 + c*16, src);
            }
            asm volatile("cp.async.commit_group;");
            asm volatile("cp.async.wait_group 2;");
        } else if (ch+1 < nch){
            asm volatile("cp.async.wait_group 1;");
        } else {
            asm volatile("cp.async.wait_group 0;");
        }
        __syncthreads();
        const uint32_t stg = sbase + buf*STAGE;
        #pragma unroll
        for (int kk=0; kk<2; kk++){
            uint32_t a_h[4][4];
            #pragma unroll
            for (int mt=0; mt<4; mt++){
                uint32_t ra = stg + (uint32_t)((wm*64 + mt*16 + (lane&15))*80 + (lane>>4)*16 + kk*32);
                ldsm4(a_h[mt], ra);
            }
            #pragma unroll
            for (int ntp=0; ntp<2; ntp++){
                uint32_t bh4[4];
                uint32_t rb = stg + 10240u +
                    (uint32_t)((wn*32 + ntp*16 + brow_off)*80 + bk_half*16 + kk*32);
                ldsm4(bh4, rb);
                #pragma unroll
                for (int mt=0; mt<4; mt++){
                    mma_fp(acc[mt][2*ntp+0], a_h[mt], &bh4[0]);
                    mma_fp(acc[mt][2*ntp+1], a_h[mt], &bh4[2]);
                }
            }
        }
        __syncthreads();
        buf++; if (buf>=3) buf=0;
    }
    const bool kmirror = (OUTMODE==3) && (bn >= 512) && (bn < 1024);
    #pragma unroll
    for (int mt=0; mt<4; mt++){
        #pragma unroll
        for (int nt=0; nt<4; nt++){
            int r0  = bm + wm*64 + mt*16 + group;
            int col = bn + wn*32 + nt*8 + tig*2;
            float bb0 = bias[col], bb1 = bias[col+1];
            #pragma unroll
            for (int hh2=0; hh2<2; hh2++){
                int row = r0 + hh2*8;
                float v0 = acc[mt][nt][hh2*2+0] + bb0;
                float v1 = acc[mt][nt][hh2*2+1] + bb1;
                if (ACT==1){ v0 = gelu_fast(v0); v1 = gelu_fast(v1); }
                if (OUTMODE==2){
                    *(uint32_t*)(C16 + (size_t)row*ldc + col) =
                        packh(__float2half(v0), __float2half(v1));
                } else {
                    *(float2*)(C + (size_t)row*ldc + col) = make_float2(v0, v1);
                    if (kmirror){
                        *(uint32_t*)(C16 + (size_t)row*DD + (col-512)) =
                            packh(__float2half(v0), __float2half(v1));
                    }
                }
            }
        }
    }
}

// one fused conversion pass: Wq|Wk|Wv|Wo|W1|W2 -> fp16 weights, x -> fp16 A
__global__ void convert_all(const float* __restrict__ Wq, const float* __restrict__ Wk,
                            const float* __restrict__ Wv, const float* __restrict__ Wo,
                            const float* __restrict__ W1, const float* __restrict__ W2,
                            const float* __restrict__ x,
                            uint16_t* __restrict__ WFH, uint16_t* __restrict__ CF)
{
    int i = blockIdx.x*256 + threadIdx.x;
    const float* src; uint16_t* dst; int rel;
    if      (i <  65536){ src=Wq; dst=WFH;        rel=i; }
    else if (i < 131072){ src=Wk; dst=WFH+1*DW;   rel=i-65536; }
    else if (i < 196608){ src=Wv; dst=WFH+2*DW;   rel=i-131072; }
    else if (i < 262144){ src=Wo; dst=WFH+3*DW;   rel=i-196608; }
    else if (i < 524288){ src=W1; dst=WFH+4*DW;   rel=i-262144; }
    else if (i < 786432){ src=W2; dst=WFH+8*DW;   rel=i-524288; }
    else                { src=x;  dst=CF;         rel=i-786432; }
    float4 v = ((const float4*)src)[rel];
    ((uint2*)dst)[rel] = make_uint2(packh(__float2half(v.x), __float2half(v.y)),
                                    packh(__float2half(v.z), __float2half(v.w)));
}

__global__ void bias_concat(const float* __restrict__ bq, const float* __restrict__ bk,
                            const float* __restrict__ bv)
{
    int t = blockIdx.x*256 + threadIdx.x;
    if (t>=QS) return;
    g_bcat[t] = (t<512)? bq[t] : (t<1024)? bk[t-512] : bv[t-1024];
}

// one warp per (bh,i): 8-lane segmented scores, 4 scores in flight per batch
__global__ void sample_scores_kernel(const int* __restrict__ idxs)
{
    int g = blockIdx.x*8 + (threadIdx.x>>5);
    int lane = threadIdx.x&31;
    int i = g&(LL-1), bh = g>>11, b = bh>>3, h = bh&7;
    int grp = lane>>3, sub = lane&7;
    const float* qp = g_QKV + (size_t)(b*LL+i)*QS + h*DK + sub*8;
    float4 qa = *(const float4*)qp;
    float4 qb = *(const float4*)(qp+4);
    int myi0 = idxs[i*SK + lane];
    int myi1 = (lane<8)? idxs[i*SK + 32 + lane] : 0;
    const uint16_t* kbase = g_Kh + (size_t)b*LL*DD + h*DK + sub*8;
    float mx = -INFINITY, sm = 0.f;
    #pragma unroll
    for (int jb=0; jb<SK; jb+=4){
        int j = jb + grp;
        int kidx = (j<32)? __shfl_sync(0xffffffffu, myi0, j)
                         : __shfl_sync(0xffffffffu, myi1, j-32);
        uint4 kw = *(const uint4*)(kbase + (size_t)kidx*DD);
        float2 k0 = h2f(kw.x), k1 = h2f(kw.y), k2 = h2f(kw.z), k3 = h2f(kw.w);
        float s = qa.x*k0.x + qa.y*k0.y + qa.z*k1.x + qa.w*k1.y
                + qb.x*k2.x + qb.y*k2.y + qb.z*k3.x + qb.w*k3.y;
        s += __shfl_xor_sync(0xffffffffu, s, 4);
        s += __shfl_xor_sync(0xffffffffu, s, 2);
        s += __shfl_xor_sync(0xffffffffu, s, 1);
        mx = fmaxf(mx, s); sm += s;
    }
    // cross-group combine (each group's mx/sm replicated across its 8 lanes)
    #pragma unroll
    for (int off=8; off<32; off<<=1){
        mx = fmaxf(mx, __shfl_xor_sync(0xffffffffu, mx, off));
        sm += __shfl_xor_sync(0xffffffffu, sm, off);
    }
    if (lane==0) g_M[bh*LL+i] = mx - sm*(1.0f/LL);
}

__global__ void topk_kernel()
{
    int bh = blockIdx.x, t = threadIdx.x;
    __shared__ uint32_t su[LL];
    __shared__ int hist[256];
    __shared__ int s_bucket, s_taken;
    __shared__ int tsum[256];
    __shared__ int s_ctr;

    for (int l=t; l<LL; l+=256){
        uint32_t s = __float_as_uint(g_M[bh*LL+l]);
        su[l] = (s & 0x80000000u)? ~s : (s | 0x80000000u);
    }
    if (t==0) s_ctr = 0;
    __syncthreads();

    uint32_t prefix = 0;
    int remaining = NTOP;
    #pragma unroll
    for (int round=0; round<4; round++){
        int shift = 24 - round*8;
        hist[t] = 0;
        __syncthreads();
        for (int l=t; l<LL; l+=256){
            uint32_t u = su[l];
            bool m = (round==0) || (((u ^ prefix) >> (shift+8)) == 0u);
            if (m) atomicAdd(&hist[(u>>shift)&255], 1);
        }
        __syncthreads();
        if (t < 32){
            int loc[8], run = 0;
            #pragma unroll
            for (int k=0; k<8; k++){
                int b = 255 - (t*8 + k);
                loc[k] = run;
                run += hist[b];
            }
            int lane_total = run;
            int scan = lane_total;
            #pragma unroll
            for (int off=1; off<32; off<<=1){
                int v = __shfl_up_sync(0xffffffffu, scan, off);
                if (t >= off) scan += v;
            }
            int excl = scan - lane_total;
            #pragma unroll
            for (int k=0; k<8; k++){
                int b = 255 - (t*8 + k);
                int cumAbove = excl + loc[k];
                if (cumAbove < remaining && remaining <= cumAbove + hist[b]){
                    s_bucket = b;
                    s_taken  = cumAbove;
                }
            }
        }
        __syncthreads();
        prefix |= ((uint32_t)s_bucket) << shift;
        remaining -= s_taken;
        __syncthreads();
    }
    const uint32_t T = prefix;
    const int r = remaining;
    const int cnt_gt = NTOP - r;

    int base = t*8, c = 0;
    #pragma unroll
    for (int k=0; k<8; k++) if (su[base+k] == T) c++;
    tsum[t] = c;
    __syncthreads();
    for (int off=1; off<256; off<<=1){
        int v = (t>=off)? tsum[t-off] : 0;
        __syncthreads();
        tsum[t] += v;
        __syncthreads();
    }
    int excl = tsum[t] - c;
    #pragma unroll
    for (int k=0; k<8; k++){
        uint32_t u = su[base+k];
        if (u > T){
            int pos = atomicAdd(&s_ctr, 1);
            g_top[bh*NTOP + pos] = base + k;
        } else if (u == T){
            if (excl < r) g_top[bh*NTOP + cnt_gt + excl] = base + k;
            excl++;
        }
    }
}

__global__ void vmean_kernel()
{
    int bh = blockIdx.x, b = bh>>3, h = bh&7;
    int t = threadIdx.x, d = t&63, r0 = t>>6;
    float s = 0.f;
    for (int l=r0; l<LL; l+=4) s += g_QKV[(size_t)(b*LL+l)*QS + 1024 + h*DK + d];
    __shared__ float red[256];
    red[t]=s; __syncthreads();
    if (t<64) g_vmean[bh*DK+t] = (red[t]+red[t+64]+red[t+128]+red[t+192])*(1.0f/LL);
}

__global__ void ctx_bcast_kernel(uint16_t* __restrict__ c16)
{
    int i = blockIdx.x*256 + threadIdx.x;
    int row = i>>8, c2 = (i&255)*2;
    int b = row>>11, h = c2>>6;
    const float* vm = g_vmean + (b*HH+h)*DK;
    *(uint32_t*)(c16 + (size_t)row*DD + c2) =
        packh(__float2half(vm[c2&63]), __float2half(vm[(c2&63)+1]));
}

__global__ void attn_scores_kernel()
{
    int kt = blockIdx.x, bh = blockIdx.y, b = bh>>3, h = bh&7;
    int t = threadIdx.x;
    __shared__ float sq[NTOP][64];
    __shared__ __align__(16) float Ks[128][68];
    __shared__ int tops[NTOP];
    if (t < NTOP) tops[t] = g_top[bh*NTOP + t];
    __syncthreads();
    const size_t qkv = (size_t)b*LL*QS;
    for (int idx=t; idx<NTOP*64; idx+=128){
        int qn = idx>>6, d = idx&63;
        sq[qn][d] = g_QKV[qkv + (size_t)tops[qn]*QS + h*DK + d];
    }
    #pragma unroll
    for (int u=0; u<16; u++){
        int f = t + u*128;
        int r = f>>4, c = (f&15)<<2;
        float4 kv = *(const float4*)(&g_QKV[qkv + (size_t)(kt*128+r)*QS + 512 + h*DK + c]);
        *(float4*)(&Ks[r][c]) = kv;
    }
    __syncthreads();
    float acc[NTOP];
    #pragma unroll
    for (int qn=0; qn<NTOP; qn++) acc[qn]=0.f;
    for (int k2=0; k2<32; k2++){
        float2 kv = *(const float2*)(&Ks[t][k2*2]);
        #pragma unroll
        for (int qn=0; qn<NTOP; qn++){
            float2 qv = *(const float2*)(&sq[qn][k2*2]);
            acc[qn] += kv.x*qv.x + kv.y*qv.y;
        }
    }
    #pragma unroll
    for (int qn=0; qn<NTOP; qn++)
        g_sc[((size_t)bh*NTOP + qn)*LL + kt*128 + t] = acc[qn];
}

__global__ void attn_stats_kernel()
{
    int bh = blockIdx.x;
    int w = threadIdx.x>>5, lane = threadIdx.x&31;
    for (int j=0; j<5; j++){
        int qn = w*5 + j;
        const float* sp = g_sc + ((size_t)bh*NTOP + qn)*LL;
        float mx = -INFINITY;
        for (int i=lane; i<LL; i+=32) mx = fmaxf(mx, sp[i]);
        #pragma unroll
        for (int off=16; off; off>>=1) mx = fmaxf(mx, __shfl_xor_sync(0xffffffffu, mx, off));
        float sum = 0.f;
        for (int i=lane; i<LL; i+=32) sum += expf(sp[i]-mx);
        #pragma unroll
        for (int off=16; off; off>>=1) sum += __shfl_xor_sync(0xffffffffu, sum, off);
        if (lane==0){ g_mx[bh*NTOP+qn]=mx; g_inv[bh*NTOP+qn]=1.0f/sum; }
    }
}

__global__ void attn_pv_kernel()
{
    extern __shared__ __align__(16) float psm[];
    float* Vs  = psm;
    float* P   = psm + 8704;
    float* smx = psm + 8704 + 5160;
    int ks = blockIdx.x, bh = blockIdx.y, b = bh>>3, h = bh&7;
    int t = threadIdx.x;
    if (t < NTOP) smx[t] = g_mx[bh*NTOP + t];
    __syncthreads();
    const size_t qkv = (size_t)b*LL*QS;
    int qg = t>>5, d2 = (t&31)*2;
    float acc[5][2];
    #pragma unroll
    for (int j=0;j<5;j++){ acc[j][0]=0.f; acc[j][1]=0.f; }
    for (int kt=0; kt<4; kt++){
        int ktg = ks*4 + kt;
        #pragma unroll
        for (int u=0; u<8; u++){
            int f = t + u*256;
            int r = f>>4, c = (f&15)<<2;
            float4 vv = *(const float4*)(&g_QKV[qkv + (size_t)(ktg*128+r)*QS + 1024 + h*DK + c]);
            *(float4*)(&Vs[r*68 + c]) = vv;
        }
        #pragma unroll
        for (int u=0; u<20; u++){
            int idx = t + u*256;
            int qn = idx>>7, row = idx&127;
            float s = g_sc[((size_t)bh*NTOP + qn)*LL + ktg*128 + row];
            P[qn*129 + row] = expf(s - smx[qn]);
        }
        __syncthreads();
        for (int row=0; row<128; row++){
            float2 vv = *(const float2*)(&Vs[row*68 + d2]);
            #pragma unroll
            for (int j=0; j<5; j++){
                float p = P[(qg*5+j)*129 + row];
                acc[j][0] += p*vv.x;
                acc[j][1] += p*vv.y;
            }
        }
        __syncthreads();
    }
    #pragma unroll
    for (int j=0; j<5; j++){
        int qn = qg*5 + j;
        float* dst = g_part + ((size_t)(ks*BH + bh)*NTOP + qn)*DK + d2;
        dst[0] = acc[j][0];
        dst[1] = acc[j][1];
    }
}

__global__ void attn_combine_kernel(uint16_t* __restrict__ c16)
{
    int bh = blockIdx.x, b = bh>>3, h = bh&7;
    int t = threadIdx.x;
    __shared__ int tops[NTOP];
    __shared__ float sinv[NTOP];
    if (t < NTOP){ tops[t] = g_top[bh*NTOP+t]; sinv[t] = g_inv[bh*NTOP+t]; }
    __syncthreads();
    for (int e=t; e<NTOP*DK/2; e+=256){
        int qn = e>>5, d2 = (e&31)*2;
        float s0=0.f, s1=0.f;
        #pragma unroll
        for (int ks=0; ks<4; ks++){
            const float* pp = g_part + ((size_t)(ks*BH + bh)*NTOP + qn)*DK + d2;
            s0 += pp[0]; s1 += pp[1];
        }
        s0 *= sinv[qn]; s1 *= sinv[qn];
        size_t o = (size_t)(b*LL + tops[qn])*DD + h*DK + d2;
        *(uint32_t*)(c16 + o) = packh(__float2half(s0), __float2half(s1));
    }
}

template<int F16OUT>
__global__ void ln_add_kernel(const float* __restrict__ X, const float* __restrict__ Y,
                              const float* __restrict__ gg, const float* __restrict__ be,
                              float* __restrict__ out, uint16_t* __restrict__ o16)
{
    int row = blockIdx.x, t = threadIdx.x;
    float4 a = ((const float4*)(X + (size_t)row*DD))[t];
    float4 bq = ((const float4*)(Y + (size_t)row*DD))[t];
    float4 v = make_float4(a.x+bq.x, a.y+bq.y, a.z+bq.z, a.w+bq.w);
    float s = v.x+v.y+v.z+v.w;
    float ss = v.x*v.x+v.y*v.y+v.z*v.z+v.w*v.w;
    __shared__ float rs[128], rq[128];
    rs[t]=s; rq[t]=ss; __syncthreads();
    for (int k=64; k; k>>=1){ if (t<k){ rs[t]+=rs[t+k]; rq[t]+=rq[t+k]; } __syncthreads(); }
    float mean = rs[0]*(1.0f/DD);
    float var  = rq[0]*(1.0f/DD) - mean*mean;
    float rstd = rsqrtf(var + 1e-5f);
    float4 g4 = ((const float4*)gg)[t], b4 = ((const float4*)be)[t];
    float4 o;
    o.x=(v.x-mean)*rstd*g4.x+b4.x; o.y=(v.y-mean)*rstd*g4.y+b4.y;
    o.z=(v.z-mean)*rstd*g4.z+b4.z; o.w=(v.w-mean)*rstd*g4.w+b4.w;
    ((float4*)(out + (size_t)row*DD))[t] = o;
    if (F16OUT){
        ((uint2*)(o16 + (size_t)row*DD))[t] = make_uint2(
            packh(__float2half(o.x), __float2half(o.y)),
            packh(__float2half(o.z), __float2half(o.w)));
    }
}

extern "C" void kernel_launch(void* const* d_in, const int* in_sizes, int n_in,
                              void* d_out, int out_size)
{
    const float* x    = (const float*)d_in[0];
    const int*   idxs = (const int*)  d_in[1];
    const float* Wq = (const float*)d_in[2];  const float* bq = (const float*)d_in[3];
    const float* Wk = (const float*)d_in[4];  const float* bk = (const float*)d_in[5];
    const float* Wv = (const float*)d_in[6];  const float* bv = (const float*)d_in[7];
    const float* Wo = (const float*)d_in[8];  const float* bo = (const float*)d_in[9];
    const float* W1 = (const float*)d_in[10]; const float* b1 = (const float*)d_in[11];
    const float* W2 = (const float*)d_in[12]; const float* b2 = (const float*)d_in[13];
    const float* g1 = (const float*)d_in[14]; const float* be1 = (const float*)d_in[15];
    const float* g2 = (const float*)d_in[16]; const float* be2 = (const float*)d_in[17];
    float* out = (float*)d_out;

    float *QKV,*H1,*T0,*BCAT;
    uint16_t *KH,*CF,*H1F,*GF,*WFH;
    cudaGetSymbolAddress((void**)&QKV, g_QKV);
    cudaGetSymbolAddress((void**)&KH, g_Kh);
    cudaGetSymbolAddress((void**)&H1, g_h1);   cudaGetSymbolAddress((void**)&T0, g_t0);
    cudaGetSymbolAddress((void**)&BCAT, g_bcat);
    cudaGetSymbolAddress((void**)&CF, g_Cf16); cudaGetSymbolAddress((void**)&H1F, g_H1f16);
    cudaGetSymbolAddress((void**)&GF, g_Gf16);
    cudaGetSymbolAddress((void**)&WFH, g_Wf16h);

    const int SMEM = 61440;
    cudaFuncSetAttribute(gemm_hmma<0,0>, cudaFuncAttributeMaxDynamicSharedMemorySize, SMEM);
    cudaFuncSetAttribute(gemm_hmma<0,3>, cudaFuncAttributeMaxDynamicSharedMemorySize, SMEM);
    cudaFuncSetAttribute(gemm_hmma<1,2>, cudaFuncAttributeMaxDynamicSharedMemorySize, SMEM);
    cudaFuncSetAttribute(attn_pv_kernel, cudaFuncAttributeMaxDynamicSharedMemorySize, 55616);

    convert_all<<<7168, 256>>>(Wq, Wk, Wv, Wo, W1, W2, x, WFH, CF);
    bias_concat<<<QS/256, 256>>>(bq, bk, bv);

    dim3 gQKV(QS/128, ROWS/128), gD(DD/128, ROWS/128), gF(FFD/128, ROWS/128);
    gemm_hmma<0,3><<<gQKV, 256, SMEM>>>(CF, WFH, BCAT, QKV, KH, DD, QS);

    sample_scores_kernel<<<ROWS*HH/8, 256>>>(idxs);
    topk_kernel<<<BH, 256>>>();
    vmean_kernel<<<BH, 256>>>();
    ctx_bcast_kernel<<<ROWS*DD/512, 256>>>(CF);
    attn_scores_kernel<<<dim3(16, BH), 128>>>();
    attn_stats_kernel<<<BH, 256>>>();
    attn_pv_kernel<<<dim3(4, BH), 256, 55616>>>();
    attn_combine_kernel<<<BH, 256>>>(CF);

    gemm_hmma<0,0><<<gD, 256, SMEM>>>(CF, WFH+3*DW, bo, T0, 0, DD, DD);
    ln_add_kernel<1><<<ROWS, 128>>>(x, T0, g1, be1, H1, H1F);

    gemm_hmma<1,2><<<gF, 256, SMEM>>>(H1F, WFH+4*DW, b1, 0, GF, DD, FFD);
    gemm_hmma<0,0><<<gD, 256, SMEM>>>(GF, WFH+8*DW, b2, T0, 0, FFD, DD);
    ln_add_kernel<0><<<ROWS, 128>>>(H1, T0, g2, be2, out, 0);
}